// round 2
// baseline (speedup 1.0000x reference)
#include <cuda_runtime.h>
#include <math.h>

#define HH 512
#define WW 512
#define KK 8
#define HWPIX (HH*WW)

// ---------------- scratch buffers (device globals; no allocation) ----------------
__device__ float g_fm [134217728];  // [K][H][W][64]  fz(0..31) | fc(32..63)
__device__ float g_t64[134217728];  // [K][H][W][64]  relu(mpn1)
__device__ float g_c32[ 67108864];  // [K][H][W][32]  relu(sup1)
__device__ float g_fuse[ 2097152];  // [H][W][K]
__device__ float g_u32 [ 8388608];  // [H][W][32]

// ======================= MLP kernel =======================
// 64 points per block, 128 threads, weights + double-buffered h in smem.
#define HSTRIDE 133
#define OFF_W1 0
#define OFF_B1 384
#define OFF_W2 512
#define OFF_B2 16896
#define OFF_W3 17024
#define OFF_B3 33792
#define OFF_W4 33920
#define OFF_B4 38016
#define OFF_HA 38048
#define OFF_HB (OFF_HA + 64*HSTRIDE)
#define OFF_XS (OFF_HB + 64*HSTRIDE)
#define MLP_SMEM_FLOATS (OFF_XS + 64*8)
#define MLP_SMEM_BYTES  (MLP_SMEM_FLOATS*4)

template<int IN, bool RELU>
__device__ __forceinline__ void mlp_step(const float* __restrict__ hin,
                                         float* __restrict__ hout,
                                         const float* __restrict__ Wf,
                                         const float* __restrict__ bf,
                                         int tu, int tp)
{
    float acc[8][8];
#pragma unroll
    for (int p = 0; p < 8; p++)
#pragma unroll
        for (int u = 0; u < 8; u++) acc[p][u] = 0.f;

#pragma unroll 2
    for (int i = 0; i < IN; i++) {
        float hv[8];
#pragma unroll
        for (int p = 0; p < 8; p++) hv[p] = hin[(tp*8 + p)*HSTRIDE + i];
        float4 w0 = *(const float4*)(Wf + i*128 + tu*8);
        float4 w1 = *(const float4*)(Wf + i*128 + tu*8 + 4);
#pragma unroll
        for (int p = 0; p < 8; p++) {
            acc[p][0] = fmaf(hv[p], w0.x, acc[p][0]);
            acc[p][1] = fmaf(hv[p], w0.y, acc[p][1]);
            acc[p][2] = fmaf(hv[p], w0.z, acc[p][2]);
            acc[p][3] = fmaf(hv[p], w0.w, acc[p][3]);
            acc[p][4] = fmaf(hv[p], w1.x, acc[p][4]);
            acc[p][5] = fmaf(hv[p], w1.y, acc[p][5]);
            acc[p][6] = fmaf(hv[p], w1.z, acc[p][6]);
            acc[p][7] = fmaf(hv[p], w1.w, acc[p][7]);
        }
    }
    float4 b0 = *(const float4*)(bf + tu*8);
    float4 b1 = *(const float4*)(bf + tu*8 + 4);
    float bb[8] = {b0.x, b0.y, b0.z, b0.w, b1.x, b1.y, b1.z, b1.w};
#pragma unroll
    for (int p = 0; p < 8; p++) {
#pragma unroll
        for (int u = 0; u < 8; u++) {
            float v = acc[p][u] + bb[u];
            if (RELU) v = fmaxf(v, 0.f);
            hout[(tp*8 + p)*HSTRIDE + tu*8 + u] = v;
        }
    }
}

__global__ void __launch_bounds__(128, 1) mlp_kernel(
    const float* __restrict__ ray, const float* __restrict__ zbufs,
    const float* __restrict__ W1, const float* __restrict__ b1,
    const float* __restrict__ W2, const float* __restrict__ b2,
    const float* __restrict__ W3, const float* __restrict__ b3,
    const float* __restrict__ W4, const float* __restrict__ b4)
{
    extern __shared__ float sm[];
    const int tid = threadIdx.x;

    // stage all weights in smem (float4 copies; all offsets 16B aligned)
    for (int i = tid; i < 96;   i += 128) ((float4*)(sm+OFF_W1))[i] = ((const float4*)W1)[i];
    for (int i = tid; i < 32;   i += 128) ((float4*)(sm+OFF_B1))[i] = ((const float4*)b1)[i];
    for (int i = tid; i < 4096; i += 128) ((float4*)(sm+OFF_W2))[i] = ((const float4*)W2)[i];
    for (int i = tid; i < 32;   i += 128) ((float4*)(sm+OFF_B2))[i] = ((const float4*)b2)[i];
    for (int i = tid; i < 4192; i += 128) ((float4*)(sm+OFF_W3))[i] = ((const float4*)W3)[i];
    for (int i = tid; i < 32;   i += 128) ((float4*)(sm+OFF_B3))[i] = ((const float4*)b3)[i];
    for (int i = tid; i < 1024; i += 128) ((float4*)(sm+OFF_W4))[i] = ((const float4*)W4)[i];
    for (int i = tid; i < 8;    i += 128) ((float4*)(sm+OFF_B4))[i] = ((const float4*)b4)[i];

    // phase A: build inputs for 64 points
    if (tid < 64) {
        int p  = blockIdx.x*64 + tid;
        int yx = p & (HWPIX - 1);
        int k  = p >> 18;
        const float* r = ray + (size_t)yx*7;
        float ox=r[0], oy=r[1], oz=r[2], dx=r[3], dy=r[4], dz=r[5], cs=r[6];
        float z = zbufs[(size_t)yx*8 + k];
        float s = z / cs;
        float* xs = sm + OFF_XS + tid*8;
        xs[0] = ox + dx*s; xs[1] = oy + dy*s; xs[2] = oz + dz*s;
        xs[3] = dx; xs[4] = dy; xs[5] = dz;
        xs[6] = (z > 0.f) ? 1.f : 0.f;
        // dirs appended as columns 128..130 of layer-3 input buffer
        sm[OFF_HB + tid*HSTRIDE + 128] = dx;
        sm[OFF_HB + tid*HSTRIDE + 129] = dy;
        sm[OFF_HB + tid*HSTRIDE + 130] = dz;
    }
    __syncthreads();

    // layer 1: 3 -> 128 (thread = unit)
    {
        float w0 = sm[OFF_W1 + 0*128 + tid];
        float w1 = sm[OFF_W1 + 1*128 + tid];
        float w2 = sm[OFF_W1 + 2*128 + tid];
        float bb = sm[OFF_B1 + tid];
        for (int t = 0; t < 64; t++) {
            const float* xs = sm + OFF_XS + t*8;
            float v = bb + xs[0]*w0 + xs[1]*w1 + xs[2]*w2;
            sm[OFF_HA + t*HSTRIDE + tid] = fmaxf(v, 0.f);
        }
    }
    __syncthreads();

    const int tu = tid & 15, tp = tid >> 4;
    // layer 2: 128 -> 128 relu  (hA -> hB)
    mlp_step<128, true>(sm+OFF_HA, sm+OFF_HB, sm+OFF_W2, sm+OFF_B2, tu, tp);
    __syncthreads();
    // layer 3: 131 -> 128 relu  (hB(+dirs) -> hA)
    mlp_step<131, true>(sm+OFF_HB, sm+OFF_HA, sm+OFF_W3, sm+OFF_B3, tu, tp);
    __syncthreads();

    // layer 4: 128 -> 32, masked, write to g_fm channels 0..31
    {
        const int tu4 = tid & 3, tp4 = tid >> 2;   // 4 unit-groups x 32 point-groups(2pts)
        float acc[2][8];
#pragma unroll
        for (int pp = 0; pp < 2; pp++)
#pragma unroll
            for (int u = 0; u < 8; u++) acc[pp][u] = 0.f;

#pragma unroll 2
        for (int i = 0; i < 128; i++) {
            float h0 = sm[OFF_HA + (tp4*2 + 0)*HSTRIDE + i];
            float h1 = sm[OFF_HA + (tp4*2 + 1)*HSTRIDE + i];
            float4 w0 = *(const float4*)(sm + OFF_W4 + i*32 + tu4*8);
            float4 w1 = *(const float4*)(sm + OFF_W4 + i*32 + tu4*8 + 4);
            acc[0][0]=fmaf(h0,w0.x,acc[0][0]); acc[0][1]=fmaf(h0,w0.y,acc[0][1]);
            acc[0][2]=fmaf(h0,w0.z,acc[0][2]); acc[0][3]=fmaf(h0,w0.w,acc[0][3]);
            acc[0][4]=fmaf(h0,w1.x,acc[0][4]); acc[0][5]=fmaf(h0,w1.y,acc[0][5]);
            acc[0][6]=fmaf(h0,w1.z,acc[0][6]); acc[0][7]=fmaf(h0,w1.w,acc[0][7]);
            acc[1][0]=fmaf(h1,w0.x,acc[1][0]); acc[1][1]=fmaf(h1,w0.y,acc[1][1]);
            acc[1][2]=fmaf(h1,w0.z,acc[1][2]); acc[1][3]=fmaf(h1,w0.w,acc[1][3]);
            acc[1][4]=fmaf(h1,w1.x,acc[1][4]); acc[1][5]=fmaf(h1,w1.y,acc[1][5]);
            acc[1][6]=fmaf(h1,w1.z,acc[1][6]); acc[1][7]=fmaf(h1,w1.w,acc[1][7]);
        }
        float4 b0 = *(const float4*)(sm + OFF_B4 + tu4*8);
        float4 b1 = *(const float4*)(sm + OFF_B4 + tu4*8 + 4);
        float bb[8] = {b0.x,b0.y,b0.z,b0.w,b1.x,b1.y,b1.z,b1.w};
#pragma unroll
        for (int pp = 0; pp < 2; pp++) {
            int t  = tp4*2 + pp;
            float mk = sm[OFF_XS + t*8 + 6];
            int p  = blockIdx.x*64 + t;
            float4 o0, o1;
            o0.x=(acc[pp][0]+bb[0])*mk; o0.y=(acc[pp][1]+bb[1])*mk;
            o0.z=(acc[pp][2]+bb[2])*mk; o0.w=(acc[pp][3]+bb[3])*mk;
            o1.x=(acc[pp][4]+bb[4])*mk; o1.y=(acc[pp][5]+bb[5])*mk;
            o1.z=(acc[pp][6]+bb[6])*mk; o1.w=(acc[pp][7]+bb[7])*mk;
            *(float4*)&g_fm[(size_t)p*64 + tu4*8]     = o0;
            *(float4*)&g_fm[(size_t)p*64 + tu4*8 + 4] = o1;
        }
    }
}

// ======================= sup1: 3 -> 32, relu =======================
__global__ void sup1_kernel(const float* __restrict__ colors,
                            const float* __restrict__ kw,
                            const float* __restrict__ bw)
{
    __shared__ float wgt[864]; // 3*3*3*32
    int tx = threadIdx.x, ty = threadIdx.y;
    int tid = ty*32 + tx;
    for (int i = tid; i < 864; i += 256) wgt[i] = kw[i];
    __syncthreads();

    int x = blockIdx.x*32 + tx, y = blockIdx.y*8 + ty, k = blockIdx.z;
    float4 acc[8];
#pragma unroll
    for (int j = 0; j < 8; j++) acc[j] = ((const float4*)bw)[j];

    for (int dy = 0; dy < 3; dy++)
    for (int dx = 0; dx < 3; dx++) {
        int iy = y + dy - 1, ix = x + dx - 1;
        if (iy < 0 || iy >= HH || ix < 0 || ix >= WW) continue;
        const float* cp = colors + ((size_t)iy*WW + ix)*24 + k*3;
        float cv[3] = {cp[0], cp[1], cp[2]};
        const float* wr = wgt + (dy*3 + dx)*96;
#pragma unroll
        for (int ic = 0; ic < 3; ic++) {
            float v = cv[ic];
            const float4* w4 = (const float4*)(wr + ic*32);
#pragma unroll
            for (int j = 0; j < 8; j++) {
                float4 w = w4[j];
                acc[j].x = fmaf(v, w.x, acc[j].x);
                acc[j].y = fmaf(v, w.y, acc[j].y);
                acc[j].z = fmaf(v, w.z, acc[j].z);
                acc[j].w = fmaf(v, w.w, acc[j].w);
            }
        }
    }
    float* dst = g_c32 + ((size_t)k*HWPIX + (size_t)y*WW + x)*32;
#pragma unroll
    for (int j = 0; j < 8; j++) {
        float4 o;
        o.x = fmaxf(acc[j].x, 0.f); o.y = fmaxf(acc[j].y, 0.f);
        o.z = fmaxf(acc[j].z, 0.f); o.w = fmaxf(acc[j].w, 0.f);
        ((float4*)dst)[j] = o;
    }
}

// ======================= sup2: 32 -> 32, no relu, write fm[32..63] ===============
// block 128 = 16x8 pixels, tile [32][10][18] (channel-major), weights 9*32*32 smem
__global__ void __launch_bounds__(128, 1) sup2_kernel(const float* __restrict__ kw,
                                                      const float* __restrict__ bw)
{
    extern __shared__ float sm[];
    float* tile = sm;            // 32*180 = 5760
    float* wgt  = sm + 5760;     // 9216
    int tid = threadIdx.x;
    for (int i = tid; i < 2304; i += 128) ((float4*)wgt)[i] = ((const float4*)kw)[i];

    int bx = blockIdx.x, by = blockIdx.y, k = blockIdx.z;
    const float* src = g_c32 + (size_t)k*HWPIX*32;
    for (int idx = tid; idx < 1440; idx += 128) {
        int c4 = idx & 7, pl = idx >> 3;
        int rr = pl/18, cc = pl - rr*18;
        int gy = by*8 + rr - 1, gx = bx*16 + cc - 1;
        float4 v = make_float4(0.f,0.f,0.f,0.f);
        if (gy >= 0 && gy < HH && gx >= 0 && gx < WW)
            v = *(const float4*)&src[((size_t)gy*WW + gx)*32 + c4*4];
        tile[(c4*4+0)*180 + pl] = v.x;
        tile[(c4*4+1)*180 + pl] = v.y;
        tile[(c4*4+2)*180 + pl] = v.z;
        tile[(c4*4+3)*180 + pl] = v.w;
    }
    __syncthreads();

    int lx = tid & 15, ly = tid >> 4;
    float4 acc[8];
#pragma unroll
    for (int j = 0; j < 8; j++) acc[j] = ((const float4*)bw)[j];

    for (int dy = 0; dy < 3; dy++)
    for (int dx = 0; dx < 3; dx++) {
        const float* wr = wgt + (size_t)(dy*3 + dx)*32*32;
        int tb = (ly + dy)*18 + (lx + dx);
        for (int ic = 0; ic < 32; ic++) {
            float v = tile[ic*180 + tb];
            const float4* w4 = (const float4*)(wr + ic*32);
#pragma unroll
            for (int j = 0; j < 8; j++) {
                float4 w = w4[j];
                acc[j].x = fmaf(v, w.x, acc[j].x);
                acc[j].y = fmaf(v, w.y, acc[j].y);
                acc[j].z = fmaf(v, w.z, acc[j].z);
                acc[j].w = fmaf(v, w.w, acc[j].w);
            }
        }
    }
    int gy = by*8 + ly, gx = bx*16 + lx;
    float* dst = g_fm + ((size_t)k*HWPIX + (size_t)gy*WW + gx)*64 + 32;
#pragma unroll
    for (int j = 0; j < 8; j++) ((float4*)dst)[j] = acc[j];
}

// ======================= mpn1: 64 -> 64, relu =======================
__global__ void __launch_bounds__(128, 1) mpn1_kernel(const float* __restrict__ kw,
                                                      const float* __restrict__ bw)
{
    extern __shared__ float sm[];
    float* tile = sm;             // 64*180 = 11520
    float* wgt  = sm + 11520;     // 36864
    int tid = threadIdx.x;
    for (int i = tid; i < 9216; i += 128) ((float4*)wgt)[i] = ((const float4*)kw)[i];

    int bx = blockIdx.x, by = blockIdx.y, k = blockIdx.z;
    const float* src = g_fm + (size_t)k*HWPIX*64;
    for (int idx = tid; idx < 2880; idx += 128) {
        int c4 = idx & 15, pl = idx >> 4;
        int rr = pl/18, cc = pl - rr*18;
        int gy = by*8 + rr - 1, gx = bx*16 + cc - 1;
        float4 v = make_float4(0.f,0.f,0.f,0.f);
        if (gy >= 0 && gy < HH && gx >= 0 && gx < WW)
            v = *(const float4*)&src[((size_t)gy*WW + gx)*64 + c4*4];
        tile[(c4*4+0)*180 + pl] = v.x;
        tile[(c4*4+1)*180 + pl] = v.y;
        tile[(c4*4+2)*180 + pl] = v.z;
        tile[(c4*4+3)*180 + pl] = v.w;
    }
    __syncthreads();

    int lx = tid & 15, ly = tid >> 4;
    float4 acc[16];
#pragma unroll
    for (int j = 0; j < 16; j++) acc[j] = ((const float4*)bw)[j];

    for (int dy = 0; dy < 3; dy++)
    for (int dx = 0; dx < 3; dx++) {
        const float* wr = wgt + (size_t)(dy*3 + dx)*64*64;
        int tb = (ly + dy)*18 + (lx + dx);
        for (int ic = 0; ic < 64; ic++) {
            float v = tile[ic*180 + tb];
            const float4* w4 = (const float4*)(wr + ic*64);
#pragma unroll
            for (int j = 0; j < 16; j++) {
                float4 w = w4[j];
                acc[j].x = fmaf(v, w.x, acc[j].x);
                acc[j].y = fmaf(v, w.y, acc[j].y);
                acc[j].z = fmaf(v, w.z, acc[j].z);
                acc[j].w = fmaf(v, w.w, acc[j].w);
            }
        }
    }
    int gy = by*8 + ly, gx = bx*16 + lx;
    float* dst = g_t64 + ((size_t)k*HWPIX + (size_t)gy*WW + gx)*64;
#pragma unroll
    for (int j = 0; j < 16; j++) {
        float4 o;
        o.x = fmaxf(acc[j].x, 0.f); o.y = fmaxf(acc[j].y, 0.f);
        o.z = fmaxf(acc[j].z, 0.f); o.w = fmaxf(acc[j].w, 0.f);
        ((float4*)dst)[j] = o;
    }
}

// ============ mpn2 + sigmoid + cumprod compositing (fused) ============
__global__ void __launch_bounds__(128, 1) mpn2_kernel(const float* __restrict__ kw,
                                                      const float* __restrict__ bw)
{
    extern __shared__ float sm[];
    float* tile = sm;
    float* wgt  = sm + 11520;
    int tid = threadIdx.x;
    for (int i = tid; i < 9216; i += 128) ((float4*)wgt)[i] = ((const float4*)kw)[i];

    int bx = blockIdx.x, by = blockIdx.y, k = blockIdx.z;
    const float* src = g_t64 + (size_t)k*HWPIX*64;
    for (int idx = tid; idx < 2880; idx += 128) {
        int c4 = idx & 15, pl = idx >> 4;
        int rr = pl/18, cc = pl - rr*18;
        int gy = by*8 + rr - 1, gx = bx*16 + cc - 1;
        float4 v = make_float4(0.f,0.f,0.f,0.f);
        if (gy >= 0 && gy < HH && gx >= 0 && gx < WW)
            v = *(const float4*)&src[((size_t)gy*WW + gx)*64 + c4*4];
        tile[(c4*4+0)*180 + pl] = v.x;
        tile[(c4*4+1)*180 + pl] = v.y;
        tile[(c4*4+2)*180 + pl] = v.z;
        tile[(c4*4+3)*180 + pl] = v.w;
    }
    __syncthreads();

    int lx = tid & 15, ly = tid >> 4;
    float4 acc[16];
#pragma unroll
    for (int j = 0; j < 16; j++) acc[j] = ((const float4*)bw)[j];

    for (int dy = 0; dy < 3; dy++)
    for (int dx = 0; dx < 3; dx++) {
        const float* wr = wgt + (size_t)(dy*3 + dx)*64*64;
        int tb = (ly + dy)*18 + (lx + dx);
        for (int ic = 0; ic < 64; ic++) {
            float v = tile[ic*180 + tb];
            const float4* w4 = (const float4*)(wr + ic*64);
#pragma unroll
            for (int j = 0; j < 16; j++) {
                float4 w = w4[j];
                acc[j].x = fmaf(v, w.x, acc[j].x);
                acc[j].y = fmaf(v, w.y, acc[j].y);
                acc[j].z = fmaf(v, w.z, acc[j].z);
                acc[j].w = fmaf(v, w.w, acc[j].w);
            }
        }
    }
    // m = sigmoid(acc); alpha_c = prod_{j<c}(1-m_j); fuse = sum fm*m*alpha
    int gy = by*8 + ly, gx = bx*16 + lx;
    const float* fmc = g_fm + ((size_t)k*HWPIX + (size_t)gy*WW + gx)*64;
    float alpha = 1.f, fuse = 0.f;
#pragma unroll
    for (int j = 0; j < 16; j++) {
        float4 f = ((const float4*)fmc)[j];
        float m;
        m = 1.f/(1.f + expf(-acc[j].x)); fuse += f.x*m*alpha; alpha *= (1.f - m);
        m = 1.f/(1.f + expf(-acc[j].y)); fuse += f.y*m*alpha; alpha *= (1.f - m);
        m = 1.f/(1.f + expf(-acc[j].z)); fuse += f.z*m*alpha; alpha *= (1.f - m);
        m = 1.f/(1.f + expf(-acc[j].w)); fuse += f.w*m*alpha; alpha *= (1.f - m);
    }
    g_fuse[((size_t)gy*WW + gx)*8 + k] = fuse;
}

// ======================= un1: 8 -> 32, relu =======================
__global__ void un1_kernel(const float* __restrict__ kw, const float* __restrict__ bw)
{
    __shared__ float wgt[2304]; // 3*3*8*32
    int tx = threadIdx.x, ty = threadIdx.y;
    int tid = ty*32 + tx;
    for (int i = tid; i < 2304; i += 256) wgt[i] = kw[i];
    __syncthreads();

    int x = blockIdx.x*32 + tx, y = blockIdx.y*8 + ty;
    float4 acc[8];
#pragma unroll
    for (int j = 0; j < 8; j++) acc[j] = ((const float4*)bw)[j];

    for (int dy = 0; dy < 3; dy++)
    for (int dx = 0; dx < 3; dx++) {
        int iy = y + dy - 1, ix = x + dx - 1;
        if (iy < 0 || iy >= HH || ix < 0 || ix >= WW) continue;
        const float* fp = g_fuse + ((size_t)iy*WW + ix)*8;
        float4 f0 = ((const float4*)fp)[0];
        float4 f1 = ((const float4*)fp)[1];
        float fv[8] = {f0.x,f0.y,f0.z,f0.w,f1.x,f1.y,f1.z,f1.w};
        const float* wr = wgt + (dy*3 + dx)*256;
#pragma unroll
        for (int ic = 0; ic < 8; ic++) {
            float v = fv[ic];
            const float4* w4 = (const float4*)(wr + ic*32);
#pragma unroll
            for (int j = 0; j < 8; j++) {
                float4 w = w4[j];
                acc[j].x = fmaf(v, w.x, acc[j].x);
                acc[j].y = fmaf(v, w.y, acc[j].y);
                acc[j].z = fmaf(v, w.z, acc[j].z);
                acc[j].w = fmaf(v, w.w, acc[j].w);
            }
        }
    }
    float* dst = g_u32 + ((size_t)y*WW + x)*32;
#pragma unroll
    for (int j = 0; j < 8; j++) {
        float4 o;
        o.x = fmaxf(acc[j].x, 0.f); o.y = fmaxf(acc[j].y, 0.f);
        o.z = fmaxf(acc[j].z, 0.f); o.w = fmaxf(acc[j].w, 0.f);
        ((float4*)dst)[j] = o;
    }
}

// ======================= un2: 32 -> 3 =======================
__global__ void un2_kernel(const float* __restrict__ kw, const float* __restrict__ bw,
                           float* __restrict__ out)
{
    __shared__ float wgt[864]; // 3*3*32*3
    int tx = threadIdx.x, ty = threadIdx.y;
    int tid = ty*32 + tx;
    for (int i = tid; i < 864; i += 256) wgt[i] = kw[i];
    __syncthreads();

    int x = blockIdx.x*32 + tx, y = blockIdx.y*8 + ty;
    float a0 = bw[0], a1 = bw[1], a2 = bw[2];

    for (int dy = 0; dy < 3; dy++)
    for (int dx = 0; dx < 3; dx++) {
        int iy = y + dy - 1, ix = x + dx - 1;
        if (iy < 0 || iy >= HH || ix < 0 || ix >= WW) continue;
        const float* up = g_u32 + ((size_t)iy*WW + ix)*32;
        const float* wr = wgt + (dy*3 + dx)*96;
#pragma unroll
        for (int ic4 = 0; ic4 < 8; ic4++) {
            float4 v = ((const float4*)up)[ic4];
            float vv[4] = {v.x, v.y, v.z, v.w};
#pragma unroll
            for (int j = 0; j < 4; j++) {
                int ic = ic4*4 + j;
                a0 = fmaf(vv[j], wr[ic*3 + 0], a0);
                a1 = fmaf(vv[j], wr[ic*3 + 1], a1);
                a2 = fmaf(vv[j], wr[ic*3 + 2], a2);
            }
        }
    }
    float* dst = out + ((size_t)y*WW + x)*3;
    dst[0] = a0; dst[1] = a1; dst[2] = a2;
}

// ======================= launch =======================
extern "C" void kernel_launch(void* const* d_in, const int* in_sizes, int n_in,
                              void* d_out, int out_size)
{
    const float* colors = (const float*)d_in[0];
    const float* ray    = (const float*)d_in[1];
    const float* zbufs  = (const float*)d_in[2];
    const float* W1 = (const float*)d_in[3];
    const float* b1 = (const float*)d_in[4];
    const float* W2 = (const float*)d_in[5];
    const float* b2 = (const float*)d_in[6];
    const float* W3 = (const float*)d_in[7];
    const float* b3 = (const float*)d_in[8];
    const float* W4 = (const float*)d_in[9];
    const float* b4 = (const float*)d_in[10];
    const float* k_sup1 = (const float*)d_in[11];
    const float* b_sup1 = (const float*)d_in[12];
    const float* k_sup2 = (const float*)d_in[13];
    const float* b_sup2 = (const float*)d_in[14];
    const float* k_mpn1 = (const float*)d_in[15];
    const float* b_mpn1 = (const float*)d_in[16];
    const float* k_mpn2 = (const float*)d_in[17];
    const float* b_mpn2 = (const float*)d_in[18];
    const float* k_un1  = (const float*)d_in[19];
    const float* b_un1  = (const float*)d_in[20];
    const float* k_un2  = (const float*)d_in[21];
    const float* b_un2  = (const float*)d_in[22];
    float* out = (float*)d_out;

    cudaFuncSetAttribute(mlp_kernel,  cudaFuncAttributeMaxDynamicSharedMemorySize, MLP_SMEM_BYTES);
    cudaFuncSetAttribute(sup2_kernel, cudaFuncAttributeMaxDynamicSharedMemorySize, 59904);
    cudaFuncSetAttribute(mpn1_kernel, cudaFuncAttributeMaxDynamicSharedMemorySize, 193536);
    cudaFuncSetAttribute(mpn2_kernel, cudaFuncAttributeMaxDynamicSharedMemorySize, 193536);

    mlp_kernel<<<32768, 128, MLP_SMEM_BYTES>>>(ray, zbufs, W1,b1, W2,b2, W3,b3, W4,b4);
    sup1_kernel<<<dim3(16,64,8), dim3(32,8)>>>(colors, k_sup1, b_sup1);
    sup2_kernel<<<dim3(32,64,8), 128, 59904>>>(k_sup2, b_sup2);
    mpn1_kernel<<<dim3(32,64,8), 128, 193536>>>(k_mpn1, b_mpn1);
    mpn2_kernel<<<dim3(32,64,8), 128, 193536>>>(k_mpn2, b_mpn2);
    un1_kernel<<<dim3(16,64), dim3(32,8)>>>(k_un1, b_un1);
    un2_kernel<<<dim3(16,64), dim3(32,8)>>>(k_un2, b_un2, out);
}

// round 4
// speedup vs baseline: 1.7243x; 1.7243x over previous
#include <cuda_runtime.h>
#include <cuda_bf16.h>
#include <cstdint>
#include <math.h>

#define HH 512
#define WW 512
#define HWPIX (HH*WW)

// ---------------- scratch (device globals) ----------------
__device__ __nv_bfloat16 g_ah[134217728];  // [8][H][W][64] fm hi
__device__ __nv_bfloat16 g_al[134217728];  // fm lo
__device__ __nv_bfloat16 g_bh[134217728];  // relu(mpn1) hi
__device__ __nv_bfloat16 g_bl[134217728];  // relu(mpn1) lo
__device__ float g_c32[67108864];          // [8][H][W][32] relu(sup1)
__device__ float g_fuse[2097152];          // [H][W][8]
__device__ float g_u32[8388608];           // [H][W][32]
__device__ __nv_bfloat16 g_w1t[73728];     // [2 terms][9 taps][oc64][ic64]
__device__ __nv_bfloat16 g_w2t[73728];

#define SWZ(off) ((off) ^ (((off) >> 3) & 0x70))

__device__ __forceinline__ uint32_t smem_u32(const void* p) {
    uint32_t a;
    asm("{ .reg .u64 t; cvta.to.shared.u64 t, %1; cvt.u32.u64 %0, t; }" : "=r"(a) : "l"(p));
    return a;
}
#define LDSM4(r0,r1,r2,r3,addr) \
    asm volatile("ldmatrix.sync.aligned.m8n8.x4.shared.b16 {%0,%1,%2,%3}, [%4];" \
        : "=r"(r0), "=r"(r1), "=r"(r2), "=r"(r3) : "r"(addr))
#define MMA16816(c,a0,a1,a2,a3,b0,b1) \
    asm volatile("mma.sync.aligned.m16n8k16.row.col.f32.bf16.bf16.f32 " \
        "{%0,%1,%2,%3},{%4,%5,%6,%7},{%8,%9},{%0,%1,%2,%3};" \
        : "+f"((c)[0]), "+f"((c)[1]), "+f"((c)[2]), "+f"((c)[3]) \
        : "r"(a0), "r"(a1), "r"(a2), "r"(a3), "r"(b0), "r"(b1))

__device__ __forceinline__ void split_store8(__nv_bfloat16* dh, __nv_bfloat16* dl, const float* v) {
    union { __nv_bfloat16 b[8]; uint4 u; } Hh, Ll;
#pragma unroll
    for (int j = 0; j < 8; j++) {
        __nv_bfloat16 hb = __float2bfloat16(v[j]);
        Hh.b[j] = hb;
        Ll.b[j] = __float2bfloat16(v[j] - __bfloat162float(hb));
    }
    *(uint4*)dh = Hh.u; *(uint4*)dl = Ll.u;
}

// ======================= MLP =======================
#define HSTRIDE 133
#define OFF_W1 0
#define OFF_B1 384
#define OFF_W2 512
#define OFF_B2 16896
#define OFF_W3 17024
#define OFF_B3 33792
#define OFF_W4 33920
#define OFF_B4 38016
#define OFF_HA 38048
#define OFF_HB (OFF_HA + 64*HSTRIDE)
#define OFF_XS (OFF_HB + 64*HSTRIDE)
#define MLP_SMEM_BYTES ((OFF_XS + 64*8)*4)

template<int IN>
__device__ __forceinline__ void mlp_step(const float* __restrict__ hin, float* __restrict__ hout,
                                         const float* __restrict__ Wf, const float* __restrict__ bf,
                                         int tu, int tp)
{
    float acc[8][8];
#pragma unroll
    for (int p = 0; p < 8; p++)
#pragma unroll
        for (int u = 0; u < 8; u++) acc[p][u] = 0.f;
#pragma unroll 2
    for (int i = 0; i < IN; i++) {
        float hv[8];
#pragma unroll
        for (int p = 0; p < 8; p++) hv[p] = hin[(tp*8 + p)*HSTRIDE + i];
        float4 w0 = *(const float4*)(Wf + i*128 + tu*8);
        float4 w1 = *(const float4*)(Wf + i*128 + tu*8 + 4);
#pragma unroll
        for (int p = 0; p < 8; p++) {
            acc[p][0]=fmaf(hv[p],w0.x,acc[p][0]); acc[p][1]=fmaf(hv[p],w0.y,acc[p][1]);
            acc[p][2]=fmaf(hv[p],w0.z,acc[p][2]); acc[p][3]=fmaf(hv[p],w0.w,acc[p][3]);
            acc[p][4]=fmaf(hv[p],w1.x,acc[p][4]); acc[p][5]=fmaf(hv[p],w1.y,acc[p][5]);
            acc[p][6]=fmaf(hv[p],w1.z,acc[p][6]); acc[p][7]=fmaf(hv[p],w1.w,acc[p][7]);
        }
    }
    float4 b0 = *(const float4*)(bf + tu*8);
    float4 b1 = *(const float4*)(bf + tu*8 + 4);
    float bb[8] = {b0.x,b0.y,b0.z,b0.w,b1.x,b1.y,b1.z,b1.w};
#pragma unroll
    for (int p = 0; p < 8; p++)
#pragma unroll
        for (int u = 0; u < 8; u++)
            hout[(tp*8 + p)*HSTRIDE + tu*8 + u] = fmaxf(acc[p][u] + bb[u], 0.f);
}

__global__ void __launch_bounds__(128, 1) mlp_kernel(
    const float* __restrict__ ray, const float* __restrict__ zbufs,
    const float* __restrict__ W1, const float* __restrict__ b1,
    const float* __restrict__ W2, const float* __restrict__ b2,
    const float* __restrict__ W3, const float* __restrict__ b3,
    const float* __restrict__ W4, const float* __restrict__ b4)
{
    extern __shared__ float sm[];
    const int tid = threadIdx.x;
    for (int i = tid; i < 96;   i += 128) ((float4*)(sm+OFF_W1))[i] = ((const float4*)W1)[i];
    for (int i = tid; i < 32;   i += 128) ((float4*)(sm+OFF_B1))[i] = ((const float4*)b1)[i];
    for (int i = tid; i < 4096; i += 128) ((float4*)(sm+OFF_W2))[i] = ((const float4*)W2)[i];
    for (int i = tid; i < 32;   i += 128) ((float4*)(sm+OFF_B2))[i] = ((const float4*)b2)[i];
    for (int i = tid; i < 4192; i += 128) ((float4*)(sm+OFF_W3))[i] = ((const float4*)W3)[i];
    for (int i = tid; i < 32;   i += 128) ((float4*)(sm+OFF_B3))[i] = ((const float4*)b3)[i];
    for (int i = tid; i < 1024; i += 128) ((float4*)(sm+OFF_W4))[i] = ((const float4*)W4)[i];
    for (int i = tid; i < 8;    i += 128) ((float4*)(sm+OFF_B4))[i] = ((const float4*)b4)[i];

    if (tid < 64) {
        int p  = blockIdx.x*64 + tid;
        int yx = p & (HWPIX - 1);
        int k  = p >> 18;
        const float* r = ray + (size_t)yx*7;
        float ox=r[0], oy=r[1], oz=r[2], dx=r[3], dy=r[4], dz=r[5], cs=r[6];
        float z = zbufs[(size_t)yx*8 + k];
        float s = z / cs;
        float* xs = sm + OFF_XS + tid*8;
        xs[0]=ox+dx*s; xs[1]=oy+dy*s; xs[2]=oz+dz*s;
        xs[3]=dx; xs[4]=dy; xs[5]=dz;
        xs[6]=(z>0.f)?1.f:0.f;
        sm[OFF_HB + tid*HSTRIDE + 128] = dx;
        sm[OFF_HB + tid*HSTRIDE + 129] = dy;
        sm[OFF_HB + tid*HSTRIDE + 130] = dz;
    }
    __syncthreads();
    {
        float w0 = sm[OFF_W1 + tid], w1 = sm[OFF_W1 + 128 + tid], w2 = sm[OFF_W1 + 256 + tid];
        float bb = sm[OFF_B1 + tid];
        for (int t = 0; t < 64; t++) {
            const float* xs = sm + OFF_XS + t*8;
            sm[OFF_HA + t*HSTRIDE + tid] = fmaxf(bb + xs[0]*w0 + xs[1]*w1 + xs[2]*w2, 0.f);
        }
    }
    __syncthreads();
    const int tu = tid & 15, tp = tid >> 4;
    mlp_step<128>(sm+OFF_HA, sm+OFF_HB, sm+OFF_W2, sm+OFF_B2, tu, tp);
    __syncthreads();
    mlp_step<131>(sm+OFF_HB, sm+OFF_HA, sm+OFF_W3, sm+OFF_B3, tu, tp);
    __syncthreads();
    {
        const int tu4 = tid & 3, tp4 = tid >> 2;
        float acc[2][8];
#pragma unroll
        for (int pp = 0; pp < 2; pp++)
#pragma unroll
            for (int u = 0; u < 8; u++) acc[pp][u] = 0.f;
#pragma unroll 2
        for (int i = 0; i < 128; i++) {
            float h0 = sm[OFF_HA + (tp4*2 + 0)*HSTRIDE + i];
            float h1 = sm[OFF_HA + (tp4*2 + 1)*HSTRIDE + i];
            float4 w0 = *(const float4*)(sm + OFF_W4 + i*32 + tu4*8);
            float4 w1 = *(const float4*)(sm + OFF_W4 + i*32 + tu4*8 + 4);
            acc[0][0]=fmaf(h0,w0.x,acc[0][0]); acc[0][1]=fmaf(h0,w0.y,acc[0][1]);
            acc[0][2]=fmaf(h0,w0.z,acc[0][2]); acc[0][3]=fmaf(h0,w0.w,acc[0][3]);
            acc[0][4]=fmaf(h0,w1.x,acc[0][4]); acc[0][5]=fmaf(h0,w1.y,acc[0][5]);
            acc[0][6]=fmaf(h0,w1.z,acc[0][6]); acc[0][7]=fmaf(h0,w1.w,acc[0][7]);
            acc[1][0]=fmaf(h1,w0.x,acc[1][0]); acc[1][1]=fmaf(h1,w0.y,acc[1][1]);
            acc[1][2]=fmaf(h1,w0.z,acc[1][2]); acc[1][3]=fmaf(h1,w0.w,acc[1][3]);
            acc[1][4]=fmaf(h1,w1.x,acc[1][4]); acc[1][5]=fmaf(h1,w1.y,acc[1][5]);
            acc[1][6]=fmaf(h1,w1.z,acc[1][6]); acc[1][7]=fmaf(h1,w1.w,acc[1][7]);
        }
        float4 b0 = *(const float4*)(sm + OFF_B4 + tu4*8);
        float4 b1 = *(const float4*)(sm + OFF_B4 + tu4*8 + 4);
        float bb[8] = {b0.x,b0.y,b0.z,b0.w,b1.x,b1.y,b1.z,b1.w};
#pragma unroll
        for (int pp = 0; pp < 2; pp++) {
            int t = tp4*2 + pp;
            float mk = sm[OFF_XS + t*8 + 6];
            size_t p = (size_t)blockIdx.x*64 + t;
            float v[8];
#pragma unroll
            for (int u = 0; u < 8; u++) v[u] = (acc[pp][u] + bb[u])*mk;
            split_store8(g_ah + p*64 + tu4*8, g_al + p*64 + tu4*8, v);
        }
    }
}

// ======================= sup1: 3 -> 32 relu =======================
__global__ void sup1_kernel(const float* __restrict__ colors,
                            const float* __restrict__ kw, const float* __restrict__ bw)
{
    __shared__ float wgt[864];
    int tx = threadIdx.x, ty = threadIdx.y, tid = ty*32 + tx;
    for (int i = tid; i < 864; i += 256) wgt[i] = kw[i];
    __syncthreads();
    int x = blockIdx.x*32 + tx, y = blockIdx.y*8 + ty, k = blockIdx.z;
    float4 acc[8];
#pragma unroll
    for (int j = 0; j < 8; j++) acc[j] = ((const float4*)bw)[j];
    for (int dy = 0; dy < 3; dy++)
    for (int dx = 0; dx < 3; dx++) {
        int iy = y + dy - 1, ix = x + dx - 1;
        if (iy < 0 || iy >= HH || ix < 0 || ix >= WW) continue;
        const float* cp = colors + ((size_t)iy*WW + ix)*24 + k*3;
        const float* wr = wgt + (dy*3 + dx)*96;
#pragma unroll
        for (int ic = 0; ic < 3; ic++) {
            float v = cp[ic];
            const float4* w4 = (const float4*)(wr + ic*32);
#pragma unroll
            for (int j = 0; j < 8; j++) {
                float4 w = w4[j];
                acc[j].x=fmaf(v,w.x,acc[j].x); acc[j].y=fmaf(v,w.y,acc[j].y);
                acc[j].z=fmaf(v,w.z,acc[j].z); acc[j].w=fmaf(v,w.w,acc[j].w);
            }
        }
    }
    float* dst = g_c32 + ((size_t)k*HWPIX + (size_t)y*WW + x)*32;
#pragma unroll
    for (int j = 0; j < 8; j++) {
        float4 o;
        o.x=fmaxf(acc[j].x,0.f); o.y=fmaxf(acc[j].y,0.f);
        o.z=fmaxf(acc[j].z,0.f); o.w=fmaxf(acc[j].w,0.f);
        ((float4*)dst)[j] = o;
    }
}

// ======================= sup2: 32 -> 32, split-store fm ch 32..63 ==============
__global__ void __launch_bounds__(128, 1) sup2_kernel(const float* __restrict__ kw,
                                                      const float* __restrict__ bw)
{
    extern __shared__ float sm[];
    float* tile = sm;           // 32*180
    float* wgt  = sm + 5760;    // 9216
    int tid = threadIdx.x;
    for (int i = tid; i < 2304; i += 128) ((float4*)wgt)[i] = ((const float4*)kw)[i];
    int bx = blockIdx.x, by = blockIdx.y, k = blockIdx.z;
    const float* src = g_c32 + (size_t)k*HWPIX*32;
    for (int idx = tid; idx < 1440; idx += 128) {
        int c4 = idx & 7, pl = idx >> 3;
        int rr = pl/18, cc = pl - rr*18;
        int gy = by*8 + rr - 1, gx = bx*16 + cc - 1;
        float4 v = make_float4(0.f,0.f,0.f,0.f);
        if (gy >= 0 && gy < HH && gx >= 0 && gx < WW)
            v = *(const float4*)&src[((size_t)gy*WW + gx)*32 + c4*4];
        tile[(c4*4+0)*180 + pl] = v.x; tile[(c4*4+1)*180 + pl] = v.y;
        tile[(c4*4+2)*180 + pl] = v.z; tile[(c4*4+3)*180 + pl] = v.w;
    }
    __syncthreads();
    int lx = tid & 15, ly = tid >> 4;
    float4 acc[8];
#pragma unroll
    for (int j = 0; j < 8; j++) acc[j] = ((const float4*)bw)[j];
    for (int dy = 0; dy < 3; dy++)
    for (int dx = 0; dx < 3; dx++) {
        const float* wr = wgt + (size_t)(dy*3 + dx)*1024;
        int tb = (ly + dy)*18 + (lx + dx);
        for (int ic = 0; ic < 32; ic++) {
            float v = tile[ic*180 + tb];
            const float4* w4 = (const float4*)(wr + ic*32);
#pragma unroll
            for (int j = 0; j < 8; j++) {
                float4 w = w4[j];
                acc[j].x=fmaf(v,w.x,acc[j].x); acc[j].y=fmaf(v,w.y,acc[j].y);
                acc[j].z=fmaf(v,w.z,acc[j].z); acc[j].w=fmaf(v,w.w,acc[j].w);
            }
        }
    }
    int gy = by*8 + ly, gx = bx*16 + lx;
    size_t px = (size_t)k*HWPIX + (size_t)gy*WW + gx;
    float v[32];
#pragma unroll
    for (int j = 0; j < 8; j++) { v[j*4]=acc[j].x; v[j*4+1]=acc[j].y; v[j*4+2]=acc[j].z; v[j*4+3]=acc[j].w; }
#pragma unroll
    for (int q = 0; q < 4; q++)
        split_store8(g_ah + px*64 + 32 + q*8, g_al + px*64 + 32 + q*8, v + q*8);
}

// ======================= weight transpose + split =======================
__global__ void wprep_kernel(const float* __restrict__ kw, int which)
{
    int idx = blockIdx.x*256 + threadIdx.x;
    if (idx >= 73728) return;
    int t = idx / 36864, r = idx % 36864;
    int p = r >> 12, q = r & 4095;
    int oc = q >> 6, ic = q & 63;
    float w = kw[((size_t)p*64 + ic)*64 + oc];
    __nv_bfloat16 hb = __float2bfloat16(w);
    __nv_bfloat16 o = t ? __float2bfloat16(w - __bfloat162float(hb)) : hb;
    (which ? g_w2t : g_w1t)[idx] = o;
}

// ===== mma.sync 64->64 3x3 conv (MODE 0: mpn1+relu, MODE 1: mpn2+fuse) =====
#define PITCH 136
#define STRIP_BYTES 52224                  // 3*136*128, atoms aligned
#define WOFF 52224
#define BOFF (WOFF + 147456)               // bias 64 floats
#define CONV_SMEM (BOFF + 256)             // 199936 bytes

template<int MODE>
__global__ void __launch_bounds__(256, 1) conv64_kernel(const float* __restrict__ bias)
{
    extern __shared__ char csm[];
    const uint32_t sb = smem_u32(csm);
    const int tid = threadIdx.x, wid = tid >> 5, lane = tid & 31;
    const int y = blockIdx.x, k = blockIdx.y;
    const int g = lane >> 2, tg = lane & 3;

    // stage weights (both terms), SW128 swizzled: [term][tap][oc][ic]
    {
        const __nv_bfloat16* ws = MODE ? g_w2t : g_w1t;
        for (int i = tid; i < 9216; i += 256) {
            uint4 v = *(const uint4*)(ws + i*8);
            *(uint4*)(csm + WOFF + SWZ(i*16)) = v;
        }
    }
    if (tid < 64) ((float*)(csm + BOFF))[tid] = bias[tid];

    const __nv_bfloat16* srcH = MODE ? g_bh : g_ah;
    const __nv_bfloat16* srcL = MODE ? g_bl : g_al;
    float* bs = (float*)(csm + BOFF);

    // per-thread ldmatrix lane offsets
    const uint32_t alane = (wid*16 + (lane & 15))*128 + (lane >> 4)*16;
    const uint32_t blane = ((lane & 7) + ((lane & 16) >> 1))*128 + (lane & 8)*2;

    for (int t = 0; t < 4; t++) {
        const int x0 = t*128;
        float acc[8][4];
#pragma unroll
        for (int s = 0; s < 8; s++)
#pragma unroll
            for (int j = 0; j < 4; j++) acc[s][j] = 0.f;

        for (int pass = 0; pass < 2; pass++) {
            const __nv_bfloat16* src = pass ? srcL : srcH;
            __syncthreads();   // protect strip from prior readers
            for (int idx = tid; idx < 3120; idx += 256) {
                int r = idx >> 3, c = idx & 7;
                int dy = r/130, sx = r - dy*130;
                int iy = y + dy - 1, ix = x0 + sx - 1;
                uint4 v = make_uint4(0,0,0,0);
                if (iy >= 0 && iy < HH && (unsigned)ix < WW)
                    v = *(const uint4*)(src + ((size_t)k*HWPIX + (size_t)iy*WW + ix)*64 + c*8);
                *(uint4*)(csm + SWZ((dy*PITCH + sx)*128 + c*16)) = v;
            }
            __syncthreads();

            const int nterm = pass ? 1 : 2;   // hi: Wh+Wl, lo: Wh only
            for (int tap = 0; tap < 9; tap++) {
                int dy = tap/3, dxo = tap - dy*3;
                uint32_t abase = (dy*PITCH + dxo)*128 + alane;
#pragma unroll
                for (int kc = 0; kc < 4; kc++) {
                    uint32_t a0,a1,a2,a3;
                    LDSM4(a0,a1,a2,a3, sb + SWZ(abase + kc*32));
                    for (int tm = 0; tm < nterm; tm++) {
                        uint32_t wb = sb + WOFF + tm*73728;
#pragma unroll
                        for (int ns = 0; ns < 4; ns++) {
                            uint32_t b0,b1,b2,b3;
                            LDSM4(b0,b1,b2,b3, wb + SWZ(tap*8192 + ns*2048 + kc*32 + blane));
                            MMA16816(acc[ns*2],   a0,a1,a2,a3, b0,b1);
                            MMA16816(acc[ns*2+1], a0,a1,a2,a3, b2,b3);
                        }
                    }
                }
            }
        }

        // ---- epilogue ----
        if (MODE == 0) {
#pragma unroll
            for (int ns = 0; ns < 8; ns++) {
                int oc = ns*8 + tg*2;
                float b0v = bs[oc], b1v = bs[oc+1];
#pragma unroll
                for (int half = 0; half < 2; half++) {
                    int px = wid*16 + g + half*8;
                    int gx = x0 + px;
                    size_t pix = (size_t)k*HWPIX + (size_t)y*WW + gx;
                    float v0 = fmaxf(acc[ns][half*2]   + b0v, 0.f);
                    float v1 = fmaxf(acc[ns][half*2+1] + b1v, 0.f);
                    union { __nv_bfloat16 b[2]; uint32_t u; } H, L;
                    H.b[0] = __float2bfloat16(v0);
                    H.b[1] = __float2bfloat16(v1);
                    L.b[0] = __float2bfloat16(v0 - __bfloat162float(H.b[0]));
                    L.b[1] = __float2bfloat16(v1 - __bfloat162float(H.b[1]));
                    *(uint32_t*)(g_bh + pix*64 + oc) = H.u;
                    *(uint32_t*)(g_bl + pix*64 + oc) = L.u;
                }
            }
        } else {
            float* fsm = (float*)csm;   // [128 px][68]
            __syncthreads();            // all warps done reading strip
#pragma unroll
            for (int ns = 0; ns < 8; ns++) {
                int oc = ns*8 + tg*2;
#pragma unroll
                for (int half = 0; half < 2; half++) {
                    int px = wid*16 + g + half*8;
                    fsm[px*68 + oc]     = acc[ns][half*2]   + bs[oc];
                    fsm[px*68 + oc + 1] = acc[ns][half*2+1] + bs[oc+1];
                }
            }
            __syncthreads();
            if (tid < 128) {
                int gx = x0 + tid;
                size_t pix = (size_t)k*HWPIX + (size_t)y*WW + gx;
                const uint4* ah4 = (const uint4*)(g_ah + pix*64);
                const uint4* al4 = (const uint4*)(g_al + pix*64);
                float alpha = 1.f, fuse = 0.f;
#pragma unroll
                for (int q = 0; q < 8; q++) {
                    union { uint4 u; __nv_bfloat16 b[8]; } Ha, La;
                    Ha.u = ah4[q]; La.u = al4[q];
#pragma unroll
                    for (int j = 0; j < 8; j++) {
                        float a = fsm[tid*68 + q*8 + j];
                        float m = 1.f/(1.f + expf(-a));
                        float f = __bfloat162float(Ha.b[j]) + __bfloat162float(La.b[j]);
                        fuse += f*m*alpha;
                        alpha *= (1.f - m);
                    }
                }
                g_fuse[((size_t)y*WW + gx)*8 + k] = fuse;
            }
            __syncthreads();
        }
    }
}

// ======================= un1: 8 -> 32 relu =======================
__global__ void un1_kernel(const float* __restrict__ kw, const float* __restrict__ bw)
{
    __shared__ float wgt[2304];
    int tx = threadIdx.x, ty = threadIdx.y, tid = ty*32 + tx;
    for (int i = tid; i < 2304; i += 256) wgt[i] = kw[i];
    __syncthreads();
    int x = blockIdx.x*32 + tx, y = blockIdx.y*8 + ty;
    float4 acc[8];
#pragma unroll
    for (int j = 0; j < 8; j++) acc[j] = ((const float4*)bw)[j];
    for (int dy = 0; dy < 3; dy++)
    for (int dx = 0; dx < 3; dx++) {
        int iy = y + dy - 1, ix = x + dx - 1;
        if (iy < 0 || iy >= HH || ix < 0 || ix >= WW) continue;
        const float* fp = g_fuse + ((size_t)iy*WW + ix)*8;
        float4 f0 = ((const float4*)fp)[0];
        float4 f1 = ((const float4*)fp)[1];
        float fv[8] = {f0.x,f0.y,f0.z,f0.w,f1.x,f1.y,f1.z,f1.w};
        const float* wr = wgt + (dy*3 + dx)*256;
#pragma unroll
        for (int ic = 0; ic < 8; ic++) {
            float v = fv[ic];
            const float4* w4 = (const float4*)(wr + ic*32);
#pragma unroll
            for (int j = 0; j < 8; j++) {
                float4 w = w4[j];
                acc[j].x=fmaf(v,w.x,acc[j].x); acc[j].y=fmaf(v,w.y,acc[j].y);
                acc[j].z=fmaf(v,w.z,acc[j].z); acc[j].w=fmaf(v,w.w,acc[j].w);
            }
        }
    }
    float* dst = g_u32 + ((size_t)y*WW + x)*32;
#pragma unroll
    for (int j = 0; j < 8; j++) {
        float4 o;
        o.x=fmaxf(acc[j].x,0.f); o.y=fmaxf(acc[j].y,0.f);
        o.z=fmaxf(acc[j].z,0.f); o.w=fmaxf(acc[j].w,0.f);
        ((float4*)dst)[j] = o;
    }
}

// ======================= un2: 32 -> 3 =======================
__global__ void un2_kernel(const float* __restrict__ kw, const float* __restrict__ bw,
                           float* __restrict__ out)
{
    __shared__ float wgt[864];
    int tx = threadIdx.x, ty = threadIdx.y, tid = ty*32 + tx;
    for (int i = tid; i < 864; i += 256) wgt[i] = kw[i];
    __syncthreads();
    int x = blockIdx.x*32 + tx, y = blockIdx.y*8 + ty;
    float a0 = bw[0], a1 = bw[1], a2 = bw[2];
    for (int dy = 0; dy < 3; dy++)
    for (int dx = 0; dx < 3; dx++) {
        int iy = y + dy - 1, ix = x + dx - 1;
        if (iy < 0 || iy >= HH || ix < 0 || ix >= WW) continue;
        const float* up = g_u32 + ((size_t)iy*WW + ix)*32;
        const float* wr = wgt + (dy*3 + dx)*96;
#pragma unroll
        for (int ic4 = 0; ic4 < 8; ic4++) {
            float4 v = ((const float4*)up)[ic4];
            float vv[4] = {v.x, v.y, v.z, v.w};
#pragma unroll
            for (int j = 0; j < 4; j++) {
                int ic = ic4*4 + j;
                a0 = fmaf(vv[j], wr[ic*3 + 0], a0);
                a1 = fmaf(vv[j], wr[ic*3 + 1], a1);
                a2 = fmaf(vv[j], wr[ic*3 + 2], a2);
            }
        }
    }
    float* dst = out + ((size_t)y*WW + x)*3;
    dst[0]=a0; dst[1]=a1; dst[2]=a2;
}

// ======================= launch =======================
extern "C" void kernel_launch(void* const* d_in, const int* in_sizes, int n_in,
                              void* d_out, int out_size)
{
    const float* colors = (const float*)d_in[0];
    const float* ray    = (const float*)d_in[1];
    const float* zbufs  = (const float*)d_in[2];
    const float* W1 = (const float*)d_in[3];  const float* b1 = (const float*)d_in[4];
    const float* W2 = (const float*)d_in[5];  const float* b2 = (const float*)d_in[6];
    const float* W3 = (const float*)d_in[7];  const float* b3 = (const float*)d_in[8];
    const float* W4 = (const float*)d_in[9];  const float* b4 = (const float*)d_in[10];
    const float* k_sup1 = (const float*)d_in[11]; const float* b_sup1 = (const float*)d_in[12];
    const float* k_sup2 = (const float*)d_in[13]; const float* b_sup2 = (const float*)d_in[14];
    const float* k_mpn1 = (const float*)d_in[15]; const float* b_mpn1 = (const float*)d_in[16];
    const float* k_mpn2 = (const float*)d_in[17]; const float* b_mpn2 = (const float*)d_in[18];
    const float* k_un1  = (const float*)d_in[19]; const float* b_un1  = (const float*)d_in[20];
    const float* k_un2  = (const float*)d_in[21]; const float* b_un2  = (const float*)d_in[22];
    float* out = (float*)d_out;

    cudaFuncSetAttribute(mlp_kernel,  cudaFuncAttributeMaxDynamicSharedMemorySize, MLP_SMEM_BYTES);
    cudaFuncSetAttribute(sup2_kernel, cudaFuncAttributeMaxDynamicSharedMemorySize, 59904);
    cudaFuncSetAttribute(conv64_kernel<0>, cudaFuncAttributeMaxDynamicSharedMemorySize, CONV_SMEM);
    cudaFuncSetAttribute(conv64_kernel<1>, cudaFuncAttributeMaxDynamicSharedMemorySize, CONV_SMEM);

    wprep_kernel<<<288, 256>>>(k_mpn1, 0);
    wprep_kernel<<<288, 256>>>(k_mpn2, 1);
    mlp_kernel<<<32768, 128, MLP_SMEM_BYTES>>>(ray, zbufs, W1,b1, W2,b2, W3,b3, W4,b4);
    sup1_kernel<<<dim3(16,64,8), dim3(32,8)>>>(colors, k_sup1, b_sup1);
    sup2_kernel<<<dim3(32,64,8), 128, 59904>>>(k_sup2, b_sup2);
    conv64_kernel<0><<<dim3(512,8), 256, CONV_SMEM>>>(b_mpn1);
    conv64_kernel<1><<<dim3(512,8), 256, CONV_SMEM>>>(b_mpn2);
    un1_kernel<<<dim3(16,64), dim3(32,8)>>>(k_un1, b_un1);
    un2_kernel<<<dim3(16,64), dim3(32,8)>>>(k_un2, b_un2, out);
}

// round 6
// speedup vs baseline: 2.6721x; 1.5497x over previous
#include <cuda_runtime.h>
#include <cuda_bf16.h>
#include <cstdint>
#include <math.h>

#define HH 512
#define WW 512
#define HWPIX (HH*WW)

// ---------------- scratch (device globals) ----------------
__device__ __nv_bfloat16 g_ah[134217728];  // [8][H][W][64] fm hi
__device__ __nv_bfloat16 g_al[134217728];  // fm lo
__device__ __nv_bfloat16 g_bh[134217728];  // relu(mpn1) hi
__device__ __nv_bfloat16 g_bl[134217728];  // relu(mpn1) lo
__device__ float g_c32[67108864];          // [8][H][W][32] relu(sup1)
__device__ float g_fuse[2097152];          // [H][W][8]
__device__ float g_u32[8388608];           // [H][W][32]
__device__ __nv_bfloat16 g_w1t[73728];     // conv mpn1 [2][9][64][64]
__device__ __nv_bfloat16 g_w2t[73728];     // conv mpn2
__device__ __nv_bfloat16 g_w2m[32768];     // mlp W2 [2][128][128] (n,k)
__device__ __nv_bfloat16 g_w3m[32768];     // mlp W3 rows 0..127
__device__ __nv_bfloat16 g_w4m[8192];      // mlp W4 [2][32][128]

#define SWZ(off) ((off) ^ (((off) >> 3) & 0x70))

__device__ __forceinline__ uint32_t smem_u32(const void* p) {
    uint32_t a;
    asm("{ .reg .u64 t; cvta.to.shared.u64 t, %1; cvt.u32.u64 %0, t; }" : "=r"(a) : "l"(p));
    return a;
}
#define LDSM4(r0,r1,r2,r3,addr) \
    asm volatile("ldmatrix.sync.aligned.m8n8.x4.shared.b16 {%0,%1,%2,%3}, [%4];" \
        : "=r"(r0), "=r"(r1), "=r"(r2), "=r"(r3) : "r"(addr))
#define MMA16816(c,a0,a1,a2,a3,b0,b1) \
    asm volatile("mma.sync.aligned.m16n8k16.row.col.f32.bf16.bf16.f32 " \
        "{%0,%1,%2,%3},{%4,%5,%6,%7},{%8,%9},{%0,%1,%2,%3};" \
        : "+f"((c)[0]), "+f"((c)[1]), "+f"((c)[2]), "+f"((c)[3]) \
        : "r"(a0), "r"(a1), "r"(a2), "r"(a3), "r"(b0), "r"(b1))

__device__ __forceinline__ void split_store8(__nv_bfloat16* dh, __nv_bfloat16* dl, const float* v) {
    union { __nv_bfloat16 b[8]; uint4 u; } Hh, Ll;
#pragma unroll
    for (int j = 0; j < 8; j++) {
        __nv_bfloat16 hb = __float2bfloat16(v[j]);
        Hh.b[j] = hb;
        Ll.b[j] = __float2bfloat16(v[j] - __bfloat162float(hb));
    }
    *(uint4*)dh = Hh.u; *(uint4*)dl = Ll.u;
}

// ======================= MLP weight prep (transpose + split) =======================
__global__ void mlpprep_kernel(const float* __restrict__ W2, const float* __restrict__ W3,
                               const float* __restrict__ W4)
{
    int idx = blockIdx.x*256 + threadIdx.x;
    if (idx >= 36864) return;
    if (idx < 16384) {
        int n = idx >> 7, k = idx & 127;
        float w = W2[k*128 + n];
        __nv_bfloat16 hb = __float2bfloat16(w);
        g_w2m[idx] = hb;
        g_w2m[16384 + idx] = __float2bfloat16(w - __bfloat162float(hb));
    } else if (idx < 32768) {
        int j = idx - 16384;
        int n = j >> 7, k = j & 127;
        float w = W3[k*128 + n];
        __nv_bfloat16 hb = __float2bfloat16(w);
        g_w3m[j] = hb;
        g_w3m[16384 + j] = __float2bfloat16(w - __bfloat162float(hb));
    } else {
        int j = idx - 32768;
        int n = j >> 7, k = j & 127;
        float w = W4[k*32 + n];
        __nv_bfloat16 hb = __float2bfloat16(w);
        g_w4m[j] = hb;
        g_w4m[4096 + j] = __float2bfloat16(w - __bfloat162float(hb));
    }
}

// ======================= tensor MLP =======================
// smem offsets (bytes)
#define MW2H 0
#define MW2L 32768
#define MW3H 65536
#define MW3L 98304
#define MW4H 131072
#define MW4L 139264
#define MAH  147456
#define MAL  163840
#define MBH  180224
#define MBL  196608
#define MXS  212992
#define MW3D 215040
#define MB1  216576
#define MB2  217088
#define MB3  217600
#define MB4  218112
#define MW1  218240
#define MLP_TC_SMEM 219776

// 3-pass split GEMM on a 64-pt tile: acc += Ah*Wh + Al*Wh + Ah*Wl
__device__ __forceinline__ void gemm64(uint32_t sb, int ahOff, int alOff, int whOff, int wlOff,
                                       int mw, int nbase, int npairs, int lane, float (*acc)[4])
{
    const int ar = mw*16 + (lane & 15);
    const uint32_t aRow = sb + ar*256;
    const int arx = ar & 7;
    const int brl = (lane & 7) + ((lane & 16) >> 1);
    const int cbk = (lane & 8) >> 3;
#pragma unroll
    for (int kc = 0; kc < 8; kc++) {
        int ca = kc*2 + (lane >> 4);
        uint32_t aoff = (uint32_t)((ca ^ arx) << 4);
        uint32_t ah0,ah1,ah2,ah3, al0,al1,al2,al3;
        LDSM4(ah0,ah1,ah2,ah3, aRow + ahOff + aoff);
        LDSM4(al0,al1,al2,al3, aRow + alOff + aoff);
#pragma unroll
        for (int ns = 0; ns < npairs; ns++) {
            int br = nbase + ns*16 + brl;
            int cb = kc*2 + cbk;
            uint32_t boff = br*256 + (uint32_t)(((cb ^ (br & 7))) << 4);
            uint32_t b0,b1,b2,b3;
            LDSM4(b0,b1,b2,b3, sb + whOff + boff);
            MMA16816(acc[ns*2],   ah0,ah1,ah2,ah3, b0,b1);
            MMA16816(acc[ns*2+1], ah0,ah1,ah2,ah3, b2,b3);
            MMA16816(acc[ns*2],   al0,al1,al2,al3, b0,b1);
            MMA16816(acc[ns*2+1], al0,al1,al2,al3, b2,b3);
            LDSM4(b0,b1,b2,b3, sb + wlOff + boff);
            MMA16816(acc[ns*2],   ah0,ah1,ah2,ah3, b0,b1);
            MMA16816(acc[ns*2+1], ah0,ah1,ah2,ah3, b2,b3);
        }
    }
}

__device__ __forceinline__ void act_store_pair(char* csm, int hOff, int lOff,
                                               int r, int n, float v0, float v1)
{
    uint32_t off = r*256 + (uint32_t)((((n>>3) ^ (r&7))) << 4) + (n&7)*2;
    union { __nv_bfloat16 b[2]; uint32_t u; } H, L;
    H.b[0] = __float2bfloat16(v0);
    H.b[1] = __float2bfloat16(v1);
    L.b[0] = __float2bfloat16(v0 - __bfloat162float(H.b[0]));
    L.b[1] = __float2bfloat16(v1 - __bfloat162float(H.b[1]));
    *(uint32_t*)(csm + hOff + off) = H.u;
    *(uint32_t*)(csm + lOff + off) = L.u;
}

__global__ void __launch_bounds__(256, 1) mlp_tc_kernel(
    const float* __restrict__ ray, const float* __restrict__ zbufs,
    const float* __restrict__ W1, const float* __restrict__ b1,
    const float* __restrict__ b2, const float* __restrict__ W3,
    const float* __restrict__ b3, const float* __restrict__ b4)
{
    extern __shared__ char csm[];
    const uint32_t sb = smem_u32(csm);
    const int tid = threadIdx.x, lane = tid & 31, wid = tid >> 5;
    const int mw = wid & 3, nh = wid >> 2;

    // stage weights (swizzled chunk layout, row stride 256B)
    for (int i = tid; i < 4096; i += 256) {
        int term = i >> 11, j = i & 2047;
        int n = j >> 4, c = j & 15;
        uint32_t doff = n*256 + (uint32_t)((c ^ (n&7)) << 4);
        uint4 v2 = *(const uint4*)(g_w2m + term*16384 + n*128 + c*8);
        *(uint4*)(csm + MW2H + term*32768 + doff) = v2;
        uint4 v3 = *(const uint4*)(g_w3m + term*16384 + n*128 + c*8);
        *(uint4*)(csm + MW3H + term*32768 + doff) = v3;
        if (n < 32) {
            uint4 v4 = *(const uint4*)(g_w4m + term*4096 + n*128 + c*8);
            *(uint4*)(csm + MW4H + term*8192 + doff) = v4;
        }
    }
    for (int i = tid; i < 128; i += 256) {
        ((float*)(csm+MB1))[i] = b1[i];
        ((float*)(csm+MB2))[i] = b2[i];
        ((float*)(csm+MB3))[i] = b3[i];
    }
    if (tid < 32) ((float*)(csm+MB4))[tid] = b4[tid];
    for (int i = tid; i < 384; i += 256) {
        ((float*)(csm+MW1))[i]  = W1[i];
        ((float*)(csm+MW3D))[i] = W3[16384 + i];   // rows 128..130 of W3, [d][n]
    }
    __syncthreads();

    float* xs = (float*)(csm + MXS);
    const float* b2s = (const float*)(csm + MB2);
    const float* b3s = (const float*)(csm + MB3);
    const float* b4s = (const float*)(csm + MB4);

    for (int t = blockIdx.x; t < 32768; t += gridDim.x) {
        if (tid < 64) {
            int p  = t*64 + tid;
            int yx = p & (HWPIX - 1);
            int k  = p >> 18;
            const float* r = ray + (size_t)yx*7;
            float ox=r[0], oy=r[1], oz=r[2], dx=r[3], dy=r[4], dz=r[5], cs=r[6];
            float z = zbufs[(size_t)yx*8 + k];
            float s = z / cs;
            float* x = xs + tid*8;
            x[0]=ox+dx*s; x[1]=oy+dy*s; x[2]=oz+dz*s;
            x[3]=dx; x[4]=dy; x[5]=dz;
            x[6]=(z>0.f)?1.f:0.f; x[7]=0.f;
        }
        __syncthreads();

        // ---- layer 1: 3 -> 128 (scalar, exact) -> bufA ----
        {
            int p = tid & 63, ug = tid >> 6;
            const float* xp = xs + p*8;
            float x0=xp[0], x1=xp[1], x2=xp[2];
            const float* w1s = (const float*)(csm + MW1);
            const float* b1s = (const float*)(csm + MB1);
            float v[8];
#pragma unroll
            for (int q = 0; q < 4; q++) {
#pragma unroll
                for (int j = 0; j < 8; j++) {
                    int u = ug*32 + q*8 + j;
                    v[j] = fmaxf(b1s[u] + x0*w1s[u] + x1*w1s[128+u] + x2*w1s[256+u], 0.f);
                }
                int c = ug*4 + q;
                uint32_t off = p*256 + (uint32_t)((c ^ (p&7)) << 4);
                split_store8((__nv_bfloat16*)(csm + MAH + off),
                             (__nv_bfloat16*)(csm + MAL + off), v);
            }
        }
        __syncthreads();

        // ---- layer 2: 128 -> 128 relu (A -> B) ----
        {
            float acc[8][4] = {};
            gemm64(sb, MAH, MAL, MW2H, MW2L, mw, nh*64, 4, lane, acc);
            int r0 = mw*16 + (lane>>2);
#pragma unroll
            for (int ns = 0; ns < 8; ns++) {
                int n = nh*64 + ns*8 + (lane&3)*2;
                float bb0 = b2s[n], bb1 = b2s[n+1];
                act_store_pair(csm, MBH, MBL, r0,   n, fmaxf(acc[ns][0]+bb0,0.f), fmaxf(acc[ns][1]+bb1,0.f));
                act_store_pair(csm, MBH, MBL, r0+8, n, fmaxf(acc[ns][2]+bb0,0.f), fmaxf(acc[ns][3]+bb1,0.f));
            }
        }
        __syncthreads();

        // ---- layer 3: 131 -> 128 relu (B -> A), dirs part scalar-exact ----
        {
            float acc[8][4] = {};
            gemm64(sb, MBH, MBL, MW3H, MW3L, mw, nh*64, 4, lane, acc);
            int r0 = mw*16 + (lane>>2);
            const float* w3d = (const float*)(csm + MW3D);
            float dx0 = xs[r0*8+3],     dy0 = xs[r0*8+4],     dz0 = xs[r0*8+5];
            float dx1 = xs[(r0+8)*8+3], dy1 = xs[(r0+8)*8+4], dz1 = xs[(r0+8)*8+5];
#pragma unroll
            for (int ns = 0; ns < 8; ns++) {
                int n = nh*64 + ns*8 + (lane&3)*2;
                float w0a=w3d[n],   w0b=w3d[128+n],   w0c=w3d[256+n];
                float w1a=w3d[n+1], w1b=w3d[128+n+1], w1c=w3d[256+n+1];
                float v0 = fmaxf(acc[ns][0] + b3s[n]   + dx0*w0a + dy0*w0b + dz0*w0c, 0.f);
                float v1 = fmaxf(acc[ns][1] + b3s[n+1] + dx0*w1a + dy0*w1b + dz0*w1c, 0.f);
                float v2 = fmaxf(acc[ns][2] + b3s[n]   + dx1*w0a + dy1*w0b + dz1*w0c, 0.f);
                float v3 = fmaxf(acc[ns][3] + b3s[n+1] + dx1*w1a + dy1*w1b + dz1*w1c, 0.f);
                act_store_pair(csm, MAH, MAL, r0,   n, v0, v1);
                act_store_pair(csm, MAH, MAL, r0+8, n, v2, v3);
            }
        }
        __syncthreads();

        // ---- layer 4: 128 -> 32, masked, split-store to global ----
        {
            float acc[2][4] = {};
            gemm64(sb, MAH, MAL, MW4H, MW4L, mw, nh*16, 1, lane, acc);
            int r0 = mw*16 + (lane>>2);
#pragma unroll
            for (int ns = 0; ns < 2; ns++) {
                int n = nh*16 + ns*8 + (lane&3)*2;
                float bb0 = b4s[n], bb1 = b4s[n+1];
#pragma unroll
                for (int hh = 0; hh < 2; hh++) {
                    int r = r0 + hh*8;
                    float mk = xs[r*8+6];
                    size_t P = (size_t)t*64 + r;
                    float v0 = (acc[ns][hh*2]   + bb0)*mk;
                    float v1 = (acc[ns][hh*2+1] + bb1)*mk;
                    union { __nv_bfloat16 b[2]; uint32_t u; } H, L;
                    H.b[0] = __float2bfloat16(v0);
                    H.b[1] = __float2bfloat16(v1);
                    L.b[0] = __float2bfloat16(v0 - __bfloat162float(H.b[0]));
                    L.b[1] = __float2bfloat16(v1 - __bfloat162float(H.b[1]));
                    *(uint32_t*)(g_ah + P*64 + n) = H.u;
                    *(uint32_t*)(g_al + P*64 + n) = L.u;
                }
            }
        }
        __syncthreads();
    }
}

// ======================= sup1: 3 -> 32 relu =======================
__global__ void sup1_kernel(const float* __restrict__ colors,
                            const float* __restrict__ kw, const float* __restrict__ bw)
{
    __shared__ float wgt[864];
    int tx = threadIdx.x, ty = threadIdx.y, tid = ty*32 + tx;
    for (int i = tid; i < 864; i += 256) wgt[i] = kw[i];
    __syncthreads();
    int x = blockIdx.x*32 + tx, y = blockIdx.y*8 + ty, k = blockIdx.z;
    float4 acc[8];
#pragma unroll
    for (int j = 0; j < 8; j++) acc[j] = ((const float4*)bw)[j];
    for (int dy = 0; dy < 3; dy++)
    for (int dx = 0; dx < 3; dx++) {
        int iy = y + dy - 1, ix = x + dx - 1;
        if (iy < 0 || iy >= HH || ix < 0 || ix >= WW) continue;
        const float* cp = colors + ((size_t)iy*WW + ix)*24 + k*3;
        const float* wr = wgt + (dy*3 + dx)*96;
#pragma unroll
        for (int ic = 0; ic < 3; ic++) {
            float v = cp[ic];
            const float4* w4 = (const float4*)(wr + ic*32);
#pragma unroll
            for (int j = 0; j < 8; j++) {
                float4 w = w4[j];
                acc[j].x=fmaf(v,w.x,acc[j].x); acc[j].y=fmaf(v,w.y,acc[j].y);
                acc[j].z=fmaf(v,w.z,acc[j].z); acc[j].w=fmaf(v,w.w,acc[j].w);
            }
        }
    }
    float* dst = g_c32 + ((size_t)k*HWPIX + (size_t)y*WW + x)*32;
#pragma unroll
    for (int j = 0; j < 8; j++) {
        float4 o;
        o.x=fmaxf(acc[j].x,0.f); o.y=fmaxf(acc[j].y,0.f);
        o.z=fmaxf(acc[j].z,0.f); o.w=fmaxf(acc[j].w,0.f);
        ((float4*)dst)[j] = o;
    }
}

// ======================= sup2: 32 -> 32, split-store fm ch 32..63 ==============
__global__ void __launch_bounds__(128, 1) sup2_kernel(const float* __restrict__ kw,
                                                      const float* __restrict__ bw)
{
    extern __shared__ float sm[];
    float* tile = sm;           // 32*180
    float* wgt  = sm + 5760;    // 9216
    int tid = threadIdx.x;
    for (int i = tid; i < 2304; i += 128) ((float4*)wgt)[i] = ((const float4*)kw)[i];
    int bx = blockIdx.x, by = blockIdx.y, k = blockIdx.z;
    const float* src = g_c32 + (size_t)k*HWPIX*32;
    for (int idx = tid; idx < 1440; idx += 128) {
        int c4 = idx & 7, pl = idx >> 3;
        int rr = pl/18, cc = pl - rr*18;
        int gy = by*8 + rr - 1, gx = bx*16 + cc - 1;
        float4 v = make_float4(0.f,0.f,0.f,0.f);
        if (gy >= 0 && gy < HH && gx >= 0 && gx < WW)
            v = *(const float4*)&src[((size_t)gy*WW + gx)*32 + c4*4];
        tile[(c4*4+0)*180 + pl] = v.x; tile[(c4*4+1)*180 + pl] = v.y;
        tile[(c4*4+2)*180 + pl] = v.z; tile[(c4*4+3)*180 + pl] = v.w;
    }
    __syncthreads();
    int lx = tid & 15, ly = tid >> 4;
    float4 acc[8];
#pragma unroll
    for (int j = 0; j < 8; j++) acc[j] = ((const float4*)bw)[j];
    for (int dy = 0; dy < 3; dy++)
    for (int dx = 0; dx < 3; dx++) {
        const float* wr = wgt + (size_t)(dy*3 + dx)*1024;
        int tb = (ly + dy)*18 + (lx + dx);
        for (int ic = 0; ic < 32; ic++) {
            float v = tile[ic*180 + tb];
            const float4* w4 = (const float4*)(wr + ic*32);
#pragma unroll
            for (int j = 0; j < 8; j++) {
                float4 w = w4[j];
                acc[j].x=fmaf(v,w.x,acc[j].x); acc[j].y=fmaf(v,w.y,acc[j].y);
                acc[j].z=fmaf(v,w.z,acc[j].z); acc[j].w=fmaf(v,w.w,acc[j].w);
            }
        }
    }
    int gy = by*8 + ly, gx = bx*16 + lx;
    size_t px = (size_t)k*HWPIX + (size_t)gy*WW + gx;
    float v[32];
#pragma unroll
    for (int j = 0; j < 8; j++) { v[j*4]=acc[j].x; v[j*4+1]=acc[j].y; v[j*4+2]=acc[j].z; v[j*4+3]=acc[j].w; }
#pragma unroll
    for (int q = 0; q < 4; q++)
        split_store8(g_ah + px*64 + 32 + q*8, g_al + px*64 + 32 + q*8, v + q*8);
}

// ======================= conv weight transpose + split =======================
__global__ void wprep_kernel(const float* __restrict__ kw, int which)
{
    int idx = blockIdx.x*256 + threadIdx.x;
    if (idx >= 73728) return;
    int t = idx / 36864, r = idx % 36864;
    int p = r >> 12, q = r & 4095;
    int oc = q >> 6, ic = q & 63;
    float w = kw[((size_t)p*64 + ic)*64 + oc];
    __nv_bfloat16 hb = __float2bfloat16(w);
    __nv_bfloat16 o = t ? __float2bfloat16(w - __bfloat162float(hb)) : hb;
    (which ? g_w2t : g_w1t)[idx] = o;
}

// ===== mma.sync 64->64 3x3 conv (MODE 0: mpn1+relu, MODE 1: mpn2+fuse) =====
#define PITCH 136
#define WOFF 52224
#define BOFF (WOFF + 147456)
#define CONV_SMEM (BOFF + 256)

template<int MODE>
__global__ void __launch_bounds__(256, 1) conv64_kernel(const float* __restrict__ bias)
{
    extern __shared__ char csm[];
    const uint32_t sb = smem_u32(csm);
    const int tid = threadIdx.x, wid = tid >> 5, lane = tid & 31;
    const int y = blockIdx.x, k = blockIdx.y;
    const int g = lane >> 2, tg = lane & 3;

    {
        const __nv_bfloat16* ws = MODE ? g_w2t : g_w1t;
        for (int i = tid; i < 9216; i += 256) {
            uint4 v = *(const uint4*)(ws + i*8);
            *(uint4*)(csm + WOFF + SWZ(i*16)) = v;
        }
    }
    if (tid < 64) ((float*)(csm + BOFF))[tid] = bias[tid];

    const __nv_bfloat16* srcH = MODE ? g_bh : g_ah;
    const __nv_bfloat16* srcL = MODE ? g_bl : g_al;
    float* bs = (float*)(csm + BOFF);

    const uint32_t alane = (wid*16 + (lane & 15))*128 + (lane >> 4)*16;
    const uint32_t blane = ((lane & 7) + ((lane & 16) >> 1))*128 + (lane & 8)*2;

    for (int t = 0; t < 4; t++) {
        const int x0 = t*128;
        float acc[8][4];
#pragma unroll
        for (int s = 0; s < 8; s++)
#pragma unroll
            for (int j = 0; j < 4; j++) acc[s][j] = 0.f;

        for (int pass = 0; pass < 2; pass++) {
            const __nv_bfloat16* src = pass ? srcL : srcH;
            __syncthreads();
            for (int idx = tid; idx < 3120; idx += 256) {
                int r = idx >> 3, c = idx & 7;
                int dy = r/130, sx = r - dy*130;
                int iy = y + dy - 1, ix = x0 + sx - 1;
                uint4 v = make_uint4(0,0,0,0);
                if (iy >= 0 && iy < HH && (unsigned)ix < WW)
                    v = *(const uint4*)(src + ((size_t)k*HWPIX + (size_t)iy*WW + ix)*64 + c*8);
                *(uint4*)(csm + SWZ((dy*PITCH + sx)*128 + c*16)) = v;
            }
            __syncthreads();

            const int nterm = pass ? 1 : 2;
            for (int tap = 0; tap < 9; tap++) {
                int dy = tap/3, dxo = tap - dy*3;
                uint32_t abase = (dy*PITCH + dxo)*128 + alane;
#pragma unroll
                for (int kc = 0; kc < 4; kc++) {
                    uint32_t a0,a1,a2,a3;
                    LDSM4(a0,a1,a2,a3, sb + SWZ(abase + kc*32));
                    for (int tm = 0; tm < nterm; tm++) {
                        uint32_t wb = sb + WOFF + tm*73728;
#pragma unroll
                        for (int ns = 0; ns < 4; ns++) {
                            uint32_t b0,b1,b2,b3;
                            LDSM4(b0,b1,b2,b3, wb + SWZ(tap*8192 + ns*2048 + kc*32 + blane));
                            MMA16816(acc[ns*2],   a0,a1,a2,a3, b0,b1);
                            MMA16816(acc[ns*2+1], a0,a1,a2,a3, b2,b3);
                        }
                    }
                }
            }
        }

        if (MODE == 0) {
#pragma unroll
            for (int ns = 0; ns < 8; ns++) {
                int oc = ns*8 + tg*2;
                float b0v = bs[oc], b1v = bs[oc+1];
#pragma unroll
                for (int half = 0; half < 2; half++) {
                    int px = wid*16 + g + half*8;
                    int gx = x0 + px;
                    size_t pix = (size_t)k*HWPIX + (size_t)y*WW + gx;
                    float v0 = fmaxf(acc[ns][half*2]   + b0v, 0.f);
                    float v1 = fmaxf(acc[ns][half*2+1] + b1v, 0.f);
                    union { __nv_bfloat16 b[2]; uint32_t u; } H, L;
                    H.b[0] = __float2bfloat16(v0);
                    H.b[1] = __float2bfloat16(v1);
                    L.b[0] = __float2bfloat16(v0 - __bfloat162float(H.b[0]));
                    L.b[1] = __float2bfloat16(v1 - __bfloat162float(H.b[1]));
                    *(uint32_t*)(g_bh + pix*64 + oc) = H.u;
                    *(uint32_t*)(g_bl + pix*64 + oc) = L.u;
                }
            }
        } else {
            float* fsm = (float*)csm;
            __syncthreads();
#pragma unroll
            for (int ns = 0; ns < 8; ns++) {
                int oc = ns*8 + tg*2;
#pragma unroll
                for (int half = 0; half < 2; half++) {
                    int px = wid*16 + g + half*8;
                    fsm[px*68 + oc]     = acc[ns][half*2]   + bs[oc];
                    fsm[px*68 + oc + 1] = acc[ns][half*2+1] + bs[oc+1];
                }
            }
            __syncthreads();
            if (tid < 128) {
                int gx = x0 + tid;
                size_t pix = (size_t)k*HWPIX + (size_t)y*WW + gx;
                const uint4* ah4 = (const uint4*)(g_ah + pix*64);
                const uint4* al4 = (const uint4*)(g_al + pix*64);
                float alpha = 1.f, fuse = 0.f;
#pragma unroll
                for (int q = 0; q < 8; q++) {
                    union { uint4 u; __nv_bfloat16 b[8]; } Ha, La;
                    Ha.u = ah4[q]; La.u = al4[q];
#pragma unroll
                    for (int j = 0; j < 8; j++) {
                        float a = fsm[tid*68 + q*8 + j];
                        float m = 1.f/(1.f + expf(-a));
                        float f = __bfloat162float(Ha.b[j]) + __bfloat162float(La.b[j]);
                        fuse += f*m*alpha;
                        alpha *= (1.f - m);
                    }
                }
                g_fuse[((size_t)y*WW + gx)*8 + k] = fuse;
            }
            __syncthreads();
        }
    }
}

// ======================= un1: 8 -> 32 relu =======================
__global__ void un1_kernel(const float* __restrict__ kw, const float* __restrict__ bw)
{
    __shared__ float wgt[2304];
    int tx = threadIdx.x, ty = threadIdx.y, tid = ty*32 + tx;
    for (int i = tid; i < 2304; i += 256) wgt[i] = kw[i];
    __syncthreads();
    int x = blockIdx.x*32 + tx, y = blockIdx.y*8 + ty;
    float4 acc[8];
#pragma unroll
    for (int j = 0; j < 8; j++) acc[j] = ((const float4*)bw)[j];
    for (int dy = 0; dy < 3; dy++)
    for (int dx = 0; dx < 3; dx++) {
        int iy = y + dy - 1, ix = x + dx - 1;
        if (iy < 0 || iy >= HH || ix < 0 || ix >= WW) continue;
        const float* fp = g_fuse + ((size_t)iy*WW + ix)*8;
        float4 f0 = ((const float4*)fp)[0];
        float4 f1 = ((const float4*)fp)[1];
        float fv[8] = {f0.x,f0.y,f0.z,f0.w,f1.x,f1.y,f1.z,f1.w};
        const float* wr = wgt + (dy*3 + dx)*256;
#pragma unroll
        for (int ic = 0; ic < 8; ic++) {
            float v = fv[ic];
            const float4* w4 = (const float4*)(wr + ic*32);
#pragma unroll
            for (int j = 0; j < 8; j++) {
                float4 w = w4[j];
                acc[j].x=fmaf(v,w.x,acc[j].x); acc[j].y=fmaf(v,w.y,acc[j].y);
                acc[j].z=fmaf(v,w.z,acc[j].z); acc[j].w=fmaf(v,w.w,acc[j].w);
            }
        }
    }
    float* dst = g_u32 + ((size_t)y*WW + x)*32;
#pragma unroll
    for (int j = 0; j < 8; j++) {
        float4 o;
        o.x=fmaxf(acc[j].x,0.f); o.y=fmaxf(acc[j].y,0.f);
        o.z=fmaxf(acc[j].z,0.f); o.w=fmaxf(acc[j].w,0.f);
        ((float4*)dst)[j] = o;
    }
}

// ======================= un2: 32 -> 3 =======================
__global__ void un2_kernel(const float* __restrict__ kw, const float* __restrict__ bw,
                           float* __restrict__ out)
{
    __shared__ float wgt[864];
    int tx = threadIdx.x, ty = threadIdx.y, tid = ty*32 + tx;
    for (int i = tid; i < 864; i += 256) wgt[i] = kw[i];
    __syncthreads();
    int x = blockIdx.x*32 + tx, y = blockIdx.y*8 + ty;
    float a0 = bw[0], a1 = bw[1], a2 = bw[2];
    for (int dy = 0; dy < 3; dy++)
    for (int dx = 0; dx < 3; dx++) {
        int iy = y + dy - 1, ix = x + dx - 1;
        if (iy < 0 || iy >= HH || ix < 0 || ix >= WW) continue;
        const float* up = g_u32 + ((size_t)iy*WW + ix)*32;
        const float* wr = wgt + (dy*3 + dx)*96;
#pragma unroll
        for (int ic4 = 0; ic4 < 8; ic4++) {
            float4 v = ((const float4*)up)[ic4];
            float vv[4] = {v.x, v.y, v.z, v.w};
#pragma unroll
            for (int j = 0; j < 4; j++) {
                int ic = ic4*4 + j;
                a0 = fmaf(vv[j], wr[ic*3 + 0], a0);
                a1 = fmaf(vv[j], wr[ic*3 + 1], a1);
                a2 = fmaf(vv[j], wr[ic*3 + 2], a2);
            }
        }
    }
    float* dst = out + ((size_t)y*WW + x)*3;
    dst[0]=a0; dst[1]=a1; dst[2]=a2;
}

// ======================= launch =======================
extern "C" void kernel_launch(void* const* d_in, const int* in_sizes, int n_in,
                              void* d_out, int out_size)
{
    const float* colors = (const float*)d_in[0];
    const float* ray    = (const float*)d_in[1];
    const float* zbufs  = (const float*)d_in[2];
    const float* W1 = (const float*)d_in[3];  const float* b1 = (const float*)d_in[4];
    const float* W2 = (const float*)d_in[5];  const float* b2 = (const float*)d_in[6];
    const float* W3 = (const float*)d_in[7];  const float* b3 = (const float*)d_in[8];
    const float* W4 = (const float*)d_in[9];  const float* b4 = (const float*)d_in[10];
    const float* k_sup1 = (const float*)d_in[11]; const float* b_sup1 = (const float*)d_in[12];
    const float* k_sup2 = (const float*)d_in[13]; const float* b_sup2 = (const float*)d_in[14];
    const float* k_mpn1 = (const float*)d_in[15]; const float* b_mpn1 = (const float*)d_in[16];
    const float* k_mpn2 = (const float*)d_in[17]; const float* b_mpn2 = (const float*)d_in[18];
    const float* k_un1  = (const float*)d_in[19]; const float* b_un1  = (const float*)d_in[20];
    const float* k_un2  = (const float*)d_in[21]; const float* b_un2  = (const float*)d_in[22];
    float* out = (float*)d_out;

    cudaFuncSetAttribute(mlp_tc_kernel, cudaFuncAttributeMaxDynamicSharedMemorySize, MLP_TC_SMEM);
    cudaFuncSetAttribute(sup2_kernel, cudaFuncAttributeMaxDynamicSharedMemorySize, 59904);
    cudaFuncSetAttribute(conv64_kernel<0>, cudaFuncAttributeMaxDynamicSharedMemorySize, CONV_SMEM);
    cudaFuncSetAttribute(conv64_kernel<1>, cudaFuncAttributeMaxDynamicSharedMemorySize, CONV_SMEM);

    mlpprep_kernel<<<144, 256>>>(W2, W3, W4);
    wprep_kernel<<<288, 256>>>(k_mpn1, 0);
    wprep_kernel<<<288, 256>>>(k_mpn2, 1);
    mlp_tc_kernel<<<148, 256, MLP_TC_SMEM>>>(ray, zbufs, W1, b1, b2, W3, b3, b4);
    sup1_kernel<<<dim3(16,64,8), dim3(32,8)>>>(colors, k_sup1, b_sup1);
    sup2_kernel<<<dim3(32,64,8), 128, 59904>>>(k_sup2, b_sup2);
    conv64_kernel<0><<<dim3(512,8), 256, CONV_SMEM>>>(b_mpn1);
    conv64_kernel<1><<<dim3(512,8), 256, CONV_SMEM>>>(b_mpn2);
    un1_kernel<<<dim3(16,64), dim3(32,8)>>>(k_un1, b_un1);
    un2_kernel<<<dim3(16,64), dim3(32,8)>>>(k_un2, b_un2, out);
}

// round 7
// speedup vs baseline: 2.8025x; 1.0488x over previous
#include <cuda_runtime.h>
#include <cuda_bf16.h>
#include <cstdint>
#include <math.h>

#define HH 512
#define WW 512
#define HWPIX (HH*WW)

// ---------------- scratch (device globals) ----------------
__device__ __nv_bfloat16 g_ah[134217728];  // [8][H][W][64] fm hi
__device__ __nv_bfloat16 g_al[134217728];  // fm lo
__device__ __nv_bfloat16 g_bh[134217728];  // sup1 out (pre-conv2), later relu(mpn1) hi
__device__ __nv_bfloat16 g_bl[134217728];  // lo
__device__ float g_fuse[2097152];          // [H][W][8]
__device__ float g_u32[8388608];           // [H][W][32]
__device__ __nv_bfloat16 g_w1t[73728];     // conv mpn1 [2][9][64][64]
__device__ __nv_bfloat16 g_w2t[73728];     // conv mpn2
__device__ __nv_bfloat16 g_wst[36864];     // conv sup2 [2][9][32][64] (ic padded)
__device__ __nv_bfloat16 g_w2m[32768];     // mlp W2 [2][128][128] (n,k)
__device__ __nv_bfloat16 g_w3m[32768];     // mlp W3 rows 0..127
__device__ __nv_bfloat16 g_w4m[8192];      // mlp W4 [2][32][128]

#define SWZ(off) ((off) ^ (((off) >> 3) & 0x70))

__device__ __forceinline__ uint32_t smem_u32(const void* p) {
    uint32_t a;
    asm("{ .reg .u64 t; cvta.to.shared.u64 t, %1; cvt.u32.u64 %0, t; }" : "=r"(a) : "l"(p));
    return a;
}
#define LDSM4(r0,r1,r2,r3,addr) \
    asm volatile("ldmatrix.sync.aligned.m8n8.x4.shared.b16 {%0,%1,%2,%3}, [%4];" \
        : "=r"(r0), "=r"(r1), "=r"(r2), "=r"(r3) : "r"(addr))
#define MMA16816(c,a0,a1,a2,a3,b0,b1) \
    asm volatile("mma.sync.aligned.m16n8k16.row.col.f32.bf16.bf16.f32 " \
        "{%0,%1,%2,%3},{%4,%5,%6,%7},{%8,%9},{%0,%1,%2,%3};" \
        : "+f"((c)[0]), "+f"((c)[1]), "+f"((c)[2]), "+f"((c)[3]) \
        : "r"(a0), "r"(a1), "r"(a2), "r"(a3), "r"(b0), "r"(b1))

__device__ __forceinline__ void split_store8(__nv_bfloat16* dh, __nv_bfloat16* dl, const float* v) {
    union { __nv_bfloat16 b[8]; uint4 u; } Hh, Ll;
#pragma unroll
    for (int j = 0; j < 8; j++) {
        __nv_bfloat16 hb = __float2bfloat16(v[j]);
        Hh.b[j] = hb;
        Ll.b[j] = __float2bfloat16(v[j] - __bfloat162float(hb));
    }
    *(uint4*)dh = Hh.u; *(uint4*)dl = Ll.u;
}

// ======================= MLP weight prep (transpose + split) =======================
__global__ void mlpprep_kernel(const float* __restrict__ W2, const float* __restrict__ W3,
                               const float* __restrict__ W4)
{
    int idx = blockIdx.x*256 + threadIdx.x;
    if (idx >= 36864) return;
    if (idx < 16384) {
        int n = idx >> 7, k = idx & 127;
        float w = W2[k*128 + n];
        __nv_bfloat16 hb = __float2bfloat16(w);
        g_w2m[idx] = hb;
        g_w2m[16384 + idx] = __float2bfloat16(w - __bfloat162float(hb));
    } else if (idx < 32768) {
        int j = idx - 16384;
        int n = j >> 7, k = j & 127;
        float w = W3[k*128 + n];
        __nv_bfloat16 hb = __float2bfloat16(w);
        g_w3m[j] = hb;
        g_w3m[16384 + j] = __float2bfloat16(w - __bfloat162float(hb));
    } else {
        int j = idx - 32768;
        int n = j >> 7, k = j & 127;
        float w = W4[k*32 + n];
        __nv_bfloat16 hb = __float2bfloat16(w);
        g_w4m[j] = hb;
        g_w4m[4096 + j] = __float2bfloat16(w - __bfloat162float(hb));
    }
}

// ======================= tensor MLP =======================
#define MW2H 0
#define MW2L 32768
#define MW3H 65536
#define MW3L 98304
#define MW4H 131072
#define MW4L 139264
#define MAH  147456
#define MAL  163840
#define MBH  180224
#define MBL  196608
#define MXS  212992
#define MW3D 215040
#define MB1  216576
#define MB2  217088
#define MB3  217600
#define MB4  218112
#define MW1  218240
#define MLP_TC_SMEM 219776

__device__ __forceinline__ void gemm64(uint32_t sb, int ahOff, int alOff, int whOff, int wlOff,
                                       int mw, int nbase, int npairs, int lane, float (*acc)[4])
{
    const int ar = mw*16 + (lane & 15);
    const uint32_t aRow = sb + ar*256;
    const int arx = ar & 7;
    const int brl = (lane & 7) + ((lane & 16) >> 1);
    const int cbk = (lane & 8) >> 3;
#pragma unroll
    for (int kc = 0; kc < 8; kc++) {
        int ca = kc*2 + (lane >> 4);
        uint32_t aoff = (uint32_t)((ca ^ arx) << 4);
        uint32_t ah0,ah1,ah2,ah3, al0,al1,al2,al3;
        LDSM4(ah0,ah1,ah2,ah3, aRow + ahOff + aoff);
        LDSM4(al0,al1,al2,al3, aRow + alOff + aoff);
#pragma unroll
        for (int ns = 0; ns < npairs; ns++) {
            int br = nbase + ns*16 + brl;
            int cb = kc*2 + cbk;
            uint32_t boff = br*256 + (uint32_t)(((cb ^ (br & 7))) << 4);
            uint32_t b0,b1,b2,b3;
            LDSM4(b0,b1,b2,b3, sb + whOff + boff);
            MMA16816(acc[ns*2],   ah0,ah1,ah2,ah3, b0,b1);
            MMA16816(acc[ns*2+1], ah0,ah1,ah2,ah3, b2,b3);
            MMA16816(acc[ns*2],   al0,al1,al2,al3, b0,b1);
            MMA16816(acc[ns*2+1], al0,al1,al2,al3, b2,b3);
            LDSM4(b0,b1,b2,b3, sb + wlOff + boff);
            MMA16816(acc[ns*2],   ah0,ah1,ah2,ah3, b0,b1);
            MMA16816(acc[ns*2+1], ah0,ah1,ah2,ah3, b2,b3);
        }
    }
}

__device__ __forceinline__ void act_store_pair(char* csm, int hOff, int lOff,
                                               int r, int n, float v0, float v1)
{
    uint32_t off = r*256 + (uint32_t)((((n>>3) ^ (r&7))) << 4) + (n&7)*2;
    union { __nv_bfloat16 b[2]; uint32_t u; } H, L;
    H.b[0] = __float2bfloat16(v0);
    H.b[1] = __float2bfloat16(v1);
    L.b[0] = __float2bfloat16(v0 - __bfloat162float(H.b[0]));
    L.b[1] = __float2bfloat16(v1 - __bfloat162float(H.b[1]));
    *(uint32_t*)(csm + hOff + off) = H.u;
    *(uint32_t*)(csm + lOff + off) = L.u;
}

__global__ void __launch_bounds__(256, 1) mlp_tc_kernel(
    const float* __restrict__ ray, const float* __restrict__ zbufs,
    const float* __restrict__ W1, const float* __restrict__ b1,
    const float* __restrict__ b2, const float* __restrict__ W3,
    const float* __restrict__ b3, const float* __restrict__ b4)
{
    extern __shared__ char csm[];
    const uint32_t sb = smem_u32(csm);
    const int tid = threadIdx.x, lane = tid & 31, wid = tid >> 5;
    const int mw = wid & 3, nh = wid >> 2;

    for (int i = tid; i < 4096; i += 256) {
        int term = i >> 11, j = i & 2047;
        int n = j >> 4, c = j & 15;
        uint32_t doff = n*256 + (uint32_t)((c ^ (n&7)) << 4);
        uint4 v2 = *(const uint4*)(g_w2m + term*16384 + n*128 + c*8);
        *(uint4*)(csm + MW2H + term*32768 + doff) = v2;
        uint4 v3 = *(const uint4*)(g_w3m + term*16384 + n*128 + c*8);
        *(uint4*)(csm + MW3H + term*32768 + doff) = v3;
        if (n < 32) {
            uint4 v4 = *(const uint4*)(g_w4m + term*4096 + n*128 + c*8);
            *(uint4*)(csm + MW4H + term*8192 + doff) = v4;
        }
    }
    for (int i = tid; i < 128; i += 256) {
        ((float*)(csm+MB1))[i] = b1[i];
        ((float*)(csm+MB2))[i] = b2[i];
        ((float*)(csm+MB3))[i] = b3[i];
    }
    if (tid < 32) ((float*)(csm+MB4))[tid] = b4[tid];
    for (int i = tid; i < 384; i += 256) {
        ((float*)(csm+MW1))[i]  = W1[i];
        ((float*)(csm+MW3D))[i] = W3[16384 + i];
    }
    __syncthreads();

    float* xs = (float*)(csm + MXS);
    const float* b2s = (const float*)(csm + MB2);
    const float* b3s = (const float*)(csm + MB3);
    const float* b4s = (const float*)(csm + MB4);

    for (int t = blockIdx.x; t < 32768; t += gridDim.x) {
        if (tid < 64) {
            int p  = t*64 + tid;
            int yx = p & (HWPIX - 1);
            int k  = p >> 18;
            const float* r = ray + (size_t)yx*7;
            float ox=r[0], oy=r[1], oz=r[2], dx=r[3], dy=r[4], dz=r[5], cs=r[6];
            float z = zbufs[(size_t)yx*8 + k];
            float s = z / cs;
            float* x = xs + tid*8;
            x[0]=ox+dx*s; x[1]=oy+dy*s; x[2]=oz+dz*s;
            x[3]=dx; x[4]=dy; x[5]=dz;
            x[6]=(z>0.f)?1.f:0.f; x[7]=0.f;
        }
        __syncthreads();

        {
            int p = tid & 63, ug = tid >> 6;
            const float* xp = xs + p*8;
            float x0=xp[0], x1=xp[1], x2=xp[2];
            const float* w1s = (const float*)(csm + MW1);
            const float* b1s = (const float*)(csm + MB1);
            float v[8];
#pragma unroll
            for (int q = 0; q < 4; q++) {
#pragma unroll
                for (int j = 0; j < 8; j++) {
                    int u = ug*32 + q*8 + j;
                    v[j] = fmaxf(b1s[u] + x0*w1s[u] + x1*w1s[128+u] + x2*w1s[256+u], 0.f);
                }
                int c = ug*4 + q;
                uint32_t off = p*256 + (uint32_t)((c ^ (p&7)) << 4);
                split_store8((__nv_bfloat16*)(csm + MAH + off),
                             (__nv_bfloat16*)(csm + MAL + off), v);
            }
        }
        __syncthreads();

        {
            float acc[8][4] = {};
            gemm64(sb, MAH, MAL, MW2H, MW2L, mw, nh*64, 4, lane, acc);
            int r0 = mw*16 + (lane>>2);
#pragma unroll
            for (int ns = 0; ns < 8; ns++) {
                int n = nh*64 + ns*8 + (lane&3)*2;
                float bb0 = b2s[n], bb1 = b2s[n+1];
                act_store_pair(csm, MBH, MBL, r0,   n, fmaxf(acc[ns][0]+bb0,0.f), fmaxf(acc[ns][1]+bb1,0.f));
                act_store_pair(csm, MBH, MBL, r0+8, n, fmaxf(acc[ns][2]+bb0,0.f), fmaxf(acc[ns][3]+bb1,0.f));
            }
        }
        __syncthreads();

        {
            float acc[8][4] = {};
            gemm64(sb, MBH, MBL, MW3H, MW3L, mw, nh*64, 4, lane, acc);
            int r0 = mw*16 + (lane>>2);
            const float* w3d = (const float*)(csm + MW3D);
            float dx0 = xs[r0*8+3],     dy0 = xs[r0*8+4],     dz0 = xs[r0*8+5];
            float dx1 = xs[(r0+8)*8+3], dy1 = xs[(r0+8)*8+4], dz1 = xs[(r0+8)*8+5];
#pragma unroll
            for (int ns = 0; ns < 8; ns++) {
                int n = nh*64 + ns*8 + (lane&3)*2;
                float w0a=w3d[n],   w0b=w3d[128+n],   w0c=w3d[256+n];
                float w1a=w3d[n+1], w1b=w3d[128+n+1], w1c=w3d[256+n+1];
                float v0 = fmaxf(acc[ns][0] + b3s[n]   + dx0*w0a + dy0*w0b + dz0*w0c, 0.f);
                float v1 = fmaxf(acc[ns][1] + b3s[n+1] + dx0*w1a + dy0*w1b + dz0*w1c, 0.f);
                float v2 = fmaxf(acc[ns][2] + b3s[n]   + dx1*w0a + dy1*w0b + dz1*w0c, 0.f);
                float v3 = fmaxf(acc[ns][3] + b3s[n+1] + dx1*w1a + dy1*w1b + dz1*w1c, 0.f);
                act_store_pair(csm, MAH, MAL, r0,   n, v0, v1);
                act_store_pair(csm, MAH, MAL, r0+8, n, v2, v3);
            }
        }
        __syncthreads();

        {
            float acc[2][4] = {};
            gemm64(sb, MAH, MAL, MW4H, MW4L, mw, nh*16, 1, lane, acc);
            int r0 = mw*16 + (lane>>2);
#pragma unroll
            for (int ns = 0; ns < 2; ns++) {
                int n = nh*16 + ns*8 + (lane&3)*2;
                float bb0 = b4s[n], bb1 = b4s[n+1];
#pragma unroll
                for (int hh = 0; hh < 2; hh++) {
                    int r = r0 + hh*8;
                    float mk = xs[r*8+6];
                    size_t P = (size_t)t*64 + r;
                    float v0 = (acc[ns][hh*2]   + bb0)*mk;
                    float v1 = (acc[ns][hh*2+1] + bb1)*mk;
                    union { __nv_bfloat16 b[2]; uint32_t u; } H, L;
                    H.b[0] = __float2bfloat16(v0);
                    H.b[1] = __float2bfloat16(v1);
                    L.b[0] = __float2bfloat16(v0 - __bfloat162float(H.b[0]));
                    L.b[1] = __float2bfloat16(v1 - __bfloat162float(H.b[1]));
                    *(uint32_t*)(g_ah + P*64 + n) = H.u;
                    *(uint32_t*)(g_al + P*64 + n) = L.u;
                }
            }
        }
        __syncthreads();
    }
}

// ======================= sup1: 3 -> 32 relu, split-store padded to 64ch ========
__global__ void sup1_kernel(const float* __restrict__ colors,
                            const float* __restrict__ kw, const float* __restrict__ bw)
{
    __shared__ float wgt[864];
    int tx = threadIdx.x, ty = threadIdx.y, tid = ty*32 + tx;
    for (int i = tid; i < 864; i += 256) wgt[i] = kw[i];
    __syncthreads();
    int x = blockIdx.x*32 + tx, y = blockIdx.y*8 + ty, k = blockIdx.z;
    float4 acc[8];
#pragma unroll
    for (int j = 0; j < 8; j++) acc[j] = ((const float4*)bw)[j];
    for (int dy = 0; dy < 3; dy++)
    for (int dx = 0; dx < 3; dx++) {
        int iy = y + dy - 1, ix = x + dx - 1;
        if (iy < 0 || iy >= HH || ix < 0 || ix >= WW) continue;
        const float* cp = colors + ((size_t)iy*WW + ix)*24 + k*3;
        const float* wr = wgt + (dy*3 + dx)*96;
#pragma unroll
        for (int ic = 0; ic < 3; ic++) {
            float v = cp[ic];
            const float4* w4 = (const float4*)(wr + ic*32);
#pragma unroll
            for (int j = 0; j < 8; j++) {
                float4 w = w4[j];
                acc[j].x=fmaf(v,w.x,acc[j].x); acc[j].y=fmaf(v,w.y,acc[j].y);
                acc[j].z=fmaf(v,w.z,acc[j].z); acc[j].w=fmaf(v,w.w,acc[j].w);
            }
        }
    }
    size_t pix = (size_t)k*HWPIX + (size_t)y*WW + x;
    float v[32];
#pragma unroll
    for (int j = 0; j < 8; j++) {
        v[j*4]  =fmaxf(acc[j].x,0.f); v[j*4+1]=fmaxf(acc[j].y,0.f);
        v[j*4+2]=fmaxf(acc[j].z,0.f); v[j*4+3]=fmaxf(acc[j].w,0.f);
    }
#pragma unroll
    for (int q = 0; q < 4; q++)
        split_store8(g_bh + pix*64 + q*8, g_bl + pix*64 + q*8, v + q*8);
    uint4 z = make_uint4(0,0,0,0);
#pragma unroll
    for (int q = 0; q < 4; q++) {
        ((uint4*)(g_bh + pix*64 + 32))[q] = z;
        ((uint4*)(g_bl + pix*64 + 32))[q] = z;
    }
}

// ======================= conv weight preps =======================
__global__ void wprep_kernel(const float* __restrict__ kw, int which)
{
    int idx = blockIdx.x*256 + threadIdx.x;
    if (idx >= 73728) return;
    int t = idx / 36864, r = idx % 36864;
    int p = r >> 12, q = r & 4095;
    int oc = q >> 6, ic = q & 63;
    float w = kw[((size_t)p*64 + ic)*64 + oc];
    __nv_bfloat16 hb = __float2bfloat16(w);
    __nv_bfloat16 o = t ? __float2bfloat16(w - __bfloat162float(hb)) : hb;
    (which ? g_w2t : g_w1t)[idx] = o;
}

// sup2 weights: [2 terms][9 taps][32 oc][64 ic padded], ic>=32 -> 0
__global__ void wprep_sup2_kernel(const float* __restrict__ kw)
{
    int idx = blockIdx.x*256 + threadIdx.x;
    if (idx >= 36864) return;
    int t = idx / 18432, r = idx % 18432;
    int tap = r >> 11, q = r & 2047;
    int oc = q >> 6, ic = q & 63;
    float w = (ic < 32) ? kw[((size_t)tap*32 + ic)*32 + oc] : 0.f;
    __nv_bfloat16 hb = __float2bfloat16(w);
    g_wst[idx] = t ? __float2bfloat16(w - __bfloat162float(hb)) : hb;
}

// ===== mma.sync 64->64 3x3 conv (MODE 0: mpn1+relu, MODE 1: mpn2+fuse) =====
#define PITCH 136
#define WOFF 52224
#define BOFF (WOFF + 147456)
#define CONV_SMEM (BOFF + 256)

template<int MODE>
__global__ void __launch_bounds__(256, 1) conv64_kernel(const float* __restrict__ bias)
{
    extern __shared__ char csm[];
    const uint32_t sb = smem_u32(csm);
    const int tid = threadIdx.x, wid = tid >> 5, lane = tid & 31;
    const int y = blockIdx.x, k = blockIdx.y;
    const int g = lane >> 2, tg = lane & 3;

    {
        const __nv_bfloat16* ws = MODE ? g_w2t : g_w1t;
        for (int i = tid; i < 9216; i += 256) {
            uint4 v = *(const uint4*)(ws + i*8);
            *(uint4*)(csm + WOFF + SWZ(i*16)) = v;
        }
    }
    if (tid < 64) ((float*)(csm + BOFF))[tid] = bias[tid];

    const __nv_bfloat16* srcH = MODE ? g_bh : g_ah;
    const __nv_bfloat16* srcL = MODE ? g_bl : g_al;
    float* bs = (float*)(csm + BOFF);

    const uint32_t alane = (wid*16 + (lane & 15))*128 + (lane >> 4)*16;
    const uint32_t blane = ((lane & 7) + ((lane & 16) >> 1))*128 + (lane & 8)*2;

    for (int t = 0; t < 4; t++) {
        const int x0 = t*128;
        float acc[8][4];
#pragma unroll
        for (int s = 0; s < 8; s++)
#pragma unroll
            for (int j = 0; j < 4; j++) acc[s][j] = 0.f;

        for (int pass = 0; pass < 2; pass++) {
            const __nv_bfloat16* src = pass ? srcL : srcH;
            __syncthreads();
            for (int idx = tid; idx < 3120; idx += 256) {
                int r = idx >> 3, c = idx & 7;
                int dy = r/130, sx = r - dy*130;
                int iy = y + dy - 1, ix = x0 + sx - 1;
                uint4 v = make_uint4(0,0,0,0);
                if (iy >= 0 && iy < HH && (unsigned)ix < WW)
                    v = *(const uint4*)(src + ((size_t)k*HWPIX + (size_t)iy*WW + ix)*64 + c*8);
                *(uint4*)(csm + SWZ((dy*PITCH + sx)*128 + c*16)) = v;
            }
            __syncthreads();

            const int nterm = pass ? 1 : 2;
            for (int tap = 0; tap < 9; tap++) {
                int dy = tap/3, dxo = tap - dy*3;
                uint32_t abase = (dy*PITCH + dxo)*128 + alane;
#pragma unroll
                for (int kc = 0; kc < 4; kc++) {
                    uint32_t a0,a1,a2,a3;
                    LDSM4(a0,a1,a2,a3, sb + SWZ(abase + kc*32));
                    for (int tm = 0; tm < nterm; tm++) {
                        uint32_t wb = sb + WOFF + tm*73728;
#pragma unroll
                        for (int ns = 0; ns < 4; ns++) {
                            uint32_t b0,b1,b2,b3;
                            LDSM4(b0,b1,b2,b3, wb + SWZ(tap*8192 + ns*2048 + kc*32 + blane));
                            MMA16816(acc[ns*2],   a0,a1,a2,a3, b0,b1);
                            MMA16816(acc[ns*2+1], a0,a1,a2,a3, b2,b3);
                        }
                    }
                }
            }
        }

        if (MODE == 0) {
#pragma unroll
            for (int ns = 0; ns < 8; ns++) {
                int oc = ns*8 + tg*2;
                float b0v = bs[oc], b1v = bs[oc+1];
#pragma unroll
                for (int half = 0; half < 2; half++) {
                    int px = wid*16 + g + half*8;
                    int gx = x0 + px;
                    size_t pix = (size_t)k*HWPIX + (size_t)y*WW + gx;
                    float v0 = fmaxf(acc[ns][half*2]   + b0v, 0.f);
                    float v1 = fmaxf(acc[ns][half*2+1] + b1v, 0.f);
                    union { __nv_bfloat16 b[2]; uint32_t u; } H, L;
                    H.b[0] = __float2bfloat16(v0);
                    H.b[1] = __float2bfloat16(v1);
                    L.b[0] = __float2bfloat16(v0 - __bfloat162float(H.b[0]));
                    L.b[1] = __float2bfloat16(v1 - __bfloat162float(H.b[1]));
                    *(uint32_t*)(g_bh + pix*64 + oc) = H.u;
                    *(uint32_t*)(g_bl + pix*64 + oc) = L.u;
                }
            }
        } else {
            float* fsm = (float*)csm;
            __syncthreads();
#pragma unroll
            for (int ns = 0; ns < 8; ns++) {
                int oc = ns*8 + tg*2;
#pragma unroll
                for (int half = 0; half < 2; half++) {
                    int px = wid*16 + g + half*8;
                    fsm[px*68 + oc]     = acc[ns][half*2]   + bs[oc];
                    fsm[px*68 + oc + 1] = acc[ns][half*2+1] + bs[oc+1];
                }
            }
            __syncthreads();
            if (tid < 128) {
                int gx = x0 + tid;
                size_t pix = (size_t)k*HWPIX + (size_t)y*WW + gx;
                const uint4* ah4 = (const uint4*)(g_ah + pix*64);
                const uint4* al4 = (const uint4*)(g_al + pix*64);
                float alpha = 1.f, fuse = 0.f;
#pragma unroll
                for (int q = 0; q < 8; q++) {
                    union { uint4 u; __nv_bfloat16 b[8]; } Ha, La;
                    Ha.u = ah4[q]; La.u = al4[q];
#pragma unroll
                    for (int j = 0; j < 8; j++) {
                        float a = fsm[tid*68 + q*8 + j];
                        float m = 1.f/(1.f + expf(-a));
                        float f = __bfloat162float(Ha.b[j]) + __bfloat162float(La.b[j]);
                        fuse += f*m*alpha;
                        alpha *= (1.f - m);
                    }
                }
                g_fuse[((size_t)y*WW + gx)*8 + k] = fuse;
            }
            __syncthreads();
        }
    }
}

// ===== sup2 tensor conv: 32 -> 32 (K=32 real, ic padded to 64), no relu =====
#define W2OFF 52224
#define B2OFF (W2OFF + 73728)
#define SUP2_SMEM (B2OFF + 128)

__global__ void __launch_bounds__(256, 1) sup2_tc_kernel(const float* __restrict__ bias)
{
    extern __shared__ char csm[];
    const uint32_t sb = smem_u32(csm);
    const int tid = threadIdx.x, wid = tid >> 5, lane = tid & 31;
    const int y = blockIdx.x, k = blockIdx.y;
    const int g = lane >> 2, tg = lane & 3;

    for (int i = tid; i < 4608; i += 256) {
        uint4 v = *(const uint4*)(g_wst + i*8);
        *(uint4*)(csm + W2OFF + SWZ(i*16)) = v;
    }
    if (tid < 32) ((float*)(csm + B2OFF))[tid] = bias[tid];
    float* bs = (float*)(csm + B2OFF);

    const uint32_t alane = (wid*16 + (lane & 15))*128 + (lane >> 4)*16;
    const uint32_t blane = ((lane & 7) + ((lane & 16) >> 1))*128 + (lane & 8)*2;

    for (int t = 0; t < 4; t++) {
        const int x0 = t*128;
        float acc[4][4];
#pragma unroll
        for (int s = 0; s < 4; s++)
#pragma unroll
            for (int j = 0; j < 4; j++) acc[s][j] = 0.f;

        for (int pass = 0; pass < 2; pass++) {
            const __nv_bfloat16* src = pass ? g_bl : g_bh;
            __syncthreads();
            for (int idx = tid; idx < 1560; idx += 256) {
                int r = idx >> 2, c = idx & 3;
                int dy = r/130, sx = r - dy*130;
                int iy = y + dy - 1, ix = x0 + sx - 1;
                uint4 v = make_uint4(0,0,0,0);
                if (iy >= 0 && iy < HH && (unsigned)ix < WW)
                    v = *(const uint4*)(src + ((size_t)k*HWPIX + (size_t)iy*WW + ix)*64 + c*8);
                *(uint4*)(csm + SWZ((dy*PITCH + sx)*128 + c*16)) = v;
            }
            __syncthreads();

            const int nterm = pass ? 1 : 2;
            for (int tap = 0; tap < 9; tap++) {
                int dy = tap/3, dxo = tap - dy*3;
                uint32_t abase = (dy*PITCH + dxo)*128 + alane;
#pragma unroll
                for (int kc = 0; kc < 2; kc++) {
                    uint32_t a0,a1,a2,a3;
                    LDSM4(a0,a1,a2,a3, sb + SWZ(abase + kc*32));
                    for (int tm = 0; tm < nterm; tm++) {
                        uint32_t wb = sb + W2OFF + tm*36864;
#pragma unroll
                        for (int ns = 0; ns < 2; ns++) {
                            uint32_t b0,b1,b2,b3;
                            LDSM4(b0,b1,b2,b3, wb + SWZ(tap*4096 + ns*2048 + kc*32 + blane));
                            MMA16816(acc[ns*2],   a0,a1,a2,a3, b0,b1);
                            MMA16816(acc[ns*2+1], a0,a1,a2,a3, b2,b3);
                        }
                    }
                }
            }
        }

        // epilogue: no relu, write fm ch 32..63 split
#pragma unroll
        for (int ns = 0; ns < 4; ns++) {
            int oc = ns*8 + tg*2;
            float b0v = bs[oc], b1v = bs[oc+1];
#pragma unroll
            for (int half = 0; half < 2; half++) {
                int px = wid*16 + g + half*8;
                int gx = x0 + px;
                size_t pix = (size_t)k*HWPIX + (size_t)y*WW + gx;
                float v0 = acc[ns][half*2]   + b0v;
                float v1 = acc[ns][half*2+1] + b1v;
                union { __nv_bfloat16 b[2]; uint32_t u; } H, L;
                H.b[0] = __float2bfloat16(v0);
                H.b[1] = __float2bfloat16(v1);
                L.b[0] = __float2bfloat16(v0 - __bfloat162float(H.b[0]));
                L.b[1] = __float2bfloat16(v1 - __bfloat162float(H.b[1]));
                *(uint32_t*)(g_ah + pix*64 + 32 + oc) = H.u;
                *(uint32_t*)(g_al + pix*64 + 32 + oc) = L.u;
            }
        }
    }
}

// ======================= un1: 8 -> 32 relu =======================
__global__ void un1_kernel(const float* __restrict__ kw, const float* __restrict__ bw)
{
    __shared__ float wgt[2304];
    int tx = threadIdx.x, ty = threadIdx.y, tid = ty*32 + tx;
    for (int i = tid; i < 2304; i += 256) wgt[i] = kw[i];
    __syncthreads();
    int x = blockIdx.x*32 + tx, y = blockIdx.y*8 + ty;
    float4 acc[8];
#pragma unroll
    for (int j = 0; j < 8; j++) acc[j] = ((const float4*)bw)[j];
    for (int dy = 0; dy < 3; dy++)
    for (int dx = 0; dx < 3; dx++) {
        int iy = y + dy - 1, ix = x + dx - 1;
        if (iy < 0 || iy >= HH || ix < 0 || ix >= WW) continue;
        const float* fp = g_fuse + ((size_t)iy*WW + ix)*8;
        float4 f0 = ((const float4*)fp)[0];
        float4 f1 = ((const float4*)fp)[1];
        float fv[8] = {f0.x,f0.y,f0.z,f0.w,f1.x,f1.y,f1.z,f1.w};
        const float* wr = wgt + (dy*3 + dx)*256;
#pragma unroll
        for (int ic = 0; ic < 8; ic++) {
            float v = fv[ic];
            const float4* w4 = (const float4*)(wr + ic*32);
#pragma unroll
            for (int j = 0; j < 8; j++) {
                float4 w = w4[j];
                acc[j].x=fmaf(v,w.x,acc[j].x); acc[j].y=fmaf(v,w.y,acc[j].y);
                acc[j].z=fmaf(v,w.z,acc[j].z); acc[j].w=fmaf(v,w.w,acc[j].w);
            }
        }
    }
    float* dst = g_u32 + ((size_t)y*WW + x)*32;
#pragma unroll
    for (int j = 0; j < 8; j++) {
        float4 o;
        o.x=fmaxf(acc[j].x,0.f); o.y=fmaxf(acc[j].y,0.f);
        o.z=fmaxf(acc[j].z,0.f); o.w=fmaxf(acc[j].w,0.f);
        ((float4*)dst)[j] = o;
    }
}

// ======================= un2: 32 -> 3 =======================
__global__ void un2_kernel(const float* __restrict__ kw, const float* __restrict__ bw,
                           float* __restrict__ out)
{
    __shared__ float wgt[864];
    int tx = threadIdx.x, ty = threadIdx.y, tid = ty*32 + tx;
    for (int i = tid; i < 864; i += 256) wgt[i] = kw[i];
    __syncthreads();
    int x = blockIdx.x*32 + tx, y = blockIdx.y*8 + ty;
    float a0 = bw[0], a1 = bw[1], a2 = bw[2];
    for (int dy = 0; dy < 3; dy++)
    for (int dx = 0; dx < 3; dx++) {
        int iy = y + dy - 1, ix = x + dx - 1;
        if (iy < 0 || iy >= HH || ix < 0 || ix >= WW) continue;
        const float* up = g_u32 + ((size_t)iy*WW + ix)*32;
        const float* wr = wgt + (dy*3 + dx)*96;
#pragma unroll
        for (int ic4 = 0; ic4 < 8; ic4++) {
            float4 v = ((const float4*)up)[ic4];
            float vv[4] = {v.x, v.y, v.z, v.w};
#pragma unroll
            for (int j = 0; j < 4; j++) {
                int ic = ic4*4 + j;
                a0 = fmaf(vv[j], wr[ic*3 + 0], a0);
                a1 = fmaf(vv[j], wr[ic*3 + 1], a1);
                a2 = fmaf(vv[j], wr[ic*3 + 2], a2);
            }
        }
    }
    float* dst = out + ((size_t)y*WW + x)*3;
    dst[0]=a0; dst[1]=a1; dst[2]=a2;
}

// ======================= launch =======================
extern "C" void kernel_launch(void* const* d_in, const int* in_sizes, int n_in,
                              void* d_out, int out_size)
{
    const float* colors = (const float*)d_in[0];
    const float* ray    = (const float*)d_in[1];
    const float* zbufs  = (const float*)d_in[2];
    const float* W1 = (const float*)d_in[3];  const float* b1 = (const float*)d_in[4];
    const float* W2 = (const float*)d_in[5];  const float* b2 = (const float*)d_in[6];
    const float* W3 = (const float*)d_in[7];  const float* b3 = (const float*)d_in[8];
    const float* W4 = (const float*)d_in[9];  const float* b4 = (const float*)d_in[10];
    const float* k_sup1 = (const float*)d_in[11]; const float* b_sup1 = (const float*)d_in[12];
    const float* k_sup2 = (const float*)d_in[13]; const float* b_sup2 = (const float*)d_in[14];
    const float* k_mpn1 = (const float*)d_in[15]; const float* b_mpn1 = (const float*)d_in[16];
    const float* k_mpn2 = (const float*)d_in[17]; const float* b_mpn2 = (const float*)d_in[18];
    const float* k_un1  = (const float*)d_in[19]; const float* b_un1  = (const float*)d_in[20];
    const float* k_un2  = (const float*)d_in[21]; const float* b_un2  = (const float*)d_in[22];
    float* out = (float*)d_out;

    cudaFuncSetAttribute(mlp_tc_kernel, cudaFuncAttributeMaxDynamicSharedMemorySize, MLP_TC_SMEM);
    cudaFuncSetAttribute(sup2_tc_kernel, cudaFuncAttributeMaxDynamicSharedMemorySize, SUP2_SMEM);
    cudaFuncSetAttribute(conv64_kernel<0>, cudaFuncAttributeMaxDynamicSharedMemorySize, CONV_SMEM);
    cudaFuncSetAttribute(conv64_kernel<1>, cudaFuncAttributeMaxDynamicSharedMemorySize, CONV_SMEM);

    mlpprep_kernel<<<144, 256>>>(W2, W3, W4);
    wprep_kernel<<<288, 256>>>(k_mpn1, 0);
    wprep_kernel<<<288, 256>>>(k_mpn2, 1);
    wprep_sup2_kernel<<<144, 256>>>(k_sup2);
    mlp_tc_kernel<<<148, 256, MLP_TC_SMEM>>>(ray, zbufs, W1, b1, b2, W3, b3, b4);
    sup1_kernel<<<dim3(16,64,8), dim3(32,8)>>>(colors, k_sup1, b_sup1);
    sup2_tc_kernel<<<dim3(512,8), 256, SUP2_SMEM>>>(b_sup2);
    conv64_kernel<0><<<dim3(512,8), 256, CONV_SMEM>>>(b_mpn1);
    conv64_kernel<1><<<dim3(512,8), 256, CONV_SMEM>>>(b_mpn2);
    un1_kernel<<<dim3(16,64), dim3(32,8)>>>(k_un1, b_un1);
    un2_kernel<<<dim3(16,64), dim3(32,8)>>>(k_un2, b_un2, out);
}

// round 8
// speedup vs baseline: 2.8564x; 1.0192x over previous
#include <cuda_runtime.h>
#include <cuda_bf16.h>
#include <cstdint>
#include <math.h>

#define HH 512
#define WW 512
#define HWPIX (HH*WW)

// ---------------- scratch (device globals) ----------------
__device__ __nv_bfloat16 g_ah[134217728];  // [8][H][W][64] fm hi
__device__ __nv_bfloat16 g_al[134217728];  // fm lo
__device__ __nv_bfloat16 g_bh[134217728];  // sup1 out, later relu(mpn1) hi
__device__ __nv_bfloat16 g_bl[134217728];  // lo
__device__ float g_fuse[2097152];          // [H][W][8]
__device__ float g_u32[8388608];           // [H][W][32]
__device__ __nv_bfloat16 g_w1t[73728];     // conv mpn1 [2][9][64][64]
__device__ __nv_bfloat16 g_w2t[73728];     // conv mpn2
__device__ __nv_bfloat16 g_wst[36864];     // conv sup2 [2][9][32][64] (ic padded)
__device__ __nv_bfloat16 g_w2m[32768];     // mlp W2 [2][128][128] (n,k)
__device__ __nv_bfloat16 g_w3m[32768];     // mlp W3 rows 0..127
__device__ __nv_bfloat16 g_w4m[8192];      // mlp W4 [2][32][128]

#define SWZ(off) ((off) ^ (((off) >> 3) & 0x70))

__device__ __forceinline__ uint32_t smem_u32(const void* p) {
    uint32_t a;
    asm("{ .reg .u64 t; cvta.to.shared.u64 t, %1; cvt.u32.u64 %0, t; }" : "=r"(a) : "l"(p));
    return a;
}
#define LDSM4(r0,r1,r2,r3,addr) \
    asm volatile("ldmatrix.sync.aligned.m8n8.x4.shared.b16 {%0,%1,%2,%3}, [%4];" \
        : "=r"(r0), "=r"(r1), "=r"(r2), "=r"(r3) : "r"(addr))
#define MMA16816(c,a0,a1,a2,a3,b0,b1) \
    asm volatile("mma.sync.aligned.m16n8k16.row.col.f32.bf16.bf16.f32 " \
        "{%0,%1,%2,%3},{%4,%5,%6,%7},{%8,%9},{%0,%1,%2,%3};" \
        : "+f"((c)[0]), "+f"((c)[1]), "+f"((c)[2]), "+f"((c)[3]) \
        : "r"(a0), "r"(a1), "r"(a2), "r"(a3), "r"(b0), "r"(b1))

__device__ __forceinline__ void split_store8(__nv_bfloat16* dh, __nv_bfloat16* dl, const float* v) {
    union { __nv_bfloat16 b[8]; uint4 u; } Hh, Ll;
#pragma unroll
    for (int j = 0; j < 8; j++) {
        __nv_bfloat16 hb = __float2bfloat16(v[j]);
        Hh.b[j] = hb;
        Ll.b[j] = __float2bfloat16(v[j] - __bfloat162float(hb));
    }
    *(uint4*)dh = Hh.u; *(uint4*)dl = Ll.u;
}

// ======================= MLP weight prep (transpose + split) =======================
__global__ void mlpprep_kernel(const float* __restrict__ W2, const float* __restrict__ W3,
                               const float* __restrict__ W4)
{
    int idx = blockIdx.x*256 + threadIdx.x;
    if (idx >= 36864) return;
    if (idx < 16384) {
        int n = idx >> 7, k = idx & 127;
        float w = W2[k*128 + n];
        __nv_bfloat16 hb = __float2bfloat16(w);
        g_w2m[idx] = hb;
        g_w2m[16384 + idx] = __float2bfloat16(w - __bfloat162float(hb));
    } else if (idx < 32768) {
        int j = idx - 16384;
        int n = j >> 7, k = j & 127;
        float w = W3[k*128 + n];
        __nv_bfloat16 hb = __float2bfloat16(w);
        g_w3m[j] = hb;
        g_w3m[16384 + j] = __float2bfloat16(w - __bfloat162float(hb));
    } else {
        int j = idx - 32768;
        int n = j >> 7, k = j & 127;
        float w = W4[k*32 + n];
        __nv_bfloat16 hb = __float2bfloat16(w);
        g_w4m[j] = hb;
        g_w4m[4096 + j] = __float2bfloat16(w - __bfloat162float(hb));
    }
}

// ======================= tensor MLP =======================
#define MW2H 0
#define MW2L 32768
#define MW3H 65536
#define MW3L 98304
#define MW4H 131072
#define MW4L 139264
#define MAH  147456
#define MAL  163840
#define MBH  180224
#define MBL  196608
#define MXS  212992
#define MW3D 215040
#define MB1  216576
#define MB2  217088
#define MB3  217600
#define MB4  218112
#define MW1  218240
#define MLP_TC_SMEM 219776

__device__ __forceinline__ void gemm64(uint32_t sb, int ahOff, int alOff, int whOff, int wlOff,
                                       int mw, int nbase, int npairs, int lane, float (*acc)[4])
{
    const int ar = mw*16 + (lane & 15);
    const uint32_t aRow = sb + ar*256;
    const int arx = ar & 7;
    const int brl = (lane & 7) + ((lane & 16) >> 1);
    const int cbk = (lane & 8) >> 3;
#pragma unroll
    for (int kc = 0; kc < 8; kc++) {
        int ca = kc*2 + (lane >> 4);
        uint32_t aoff = (uint32_t)((ca ^ arx) << 4);
        uint32_t ah0,ah1,ah2,ah3, al0,al1,al2,al3;
        LDSM4(ah0,ah1,ah2,ah3, aRow + ahOff + aoff);
        LDSM4(al0,al1,al2,al3, aRow + alOff + aoff);
#pragma unroll
        for (int ns = 0; ns < npairs; ns++) {
            int br = nbase + ns*16 + brl;
            int cb = kc*2 + cbk;
            uint32_t boff = br*256 + (uint32_t)(((cb ^ (br & 7))) << 4);
            uint32_t b0,b1,b2,b3;
            LDSM4(b0,b1,b2,b3, sb + whOff + boff);
            MMA16816(acc[ns*2],   ah0,ah1,ah2,ah3, b0,b1);
            MMA16816(acc[ns*2+1], ah0,ah1,ah2,ah3, b2,b3);
            MMA16816(acc[ns*2],   al0,al1,al2,al3, b0,b1);
            MMA16816(acc[ns*2+1], al0,al1,al2,al3, b2,b3);
            LDSM4(b0,b1,b2,b3, sb + wlOff + boff);
            MMA16816(acc[ns*2],   ah0,ah1,ah2,ah3, b0,b1);
            MMA16816(acc[ns*2+1], ah0,ah1,ah2,ah3, b2,b3);
        }
    }
}

__device__ __forceinline__ void act_store_pair(char* csm, int hOff, int lOff,
                                               int r, int n, float v0, float v1)
{
    uint32_t off = r*256 + (uint32_t)((((n>>3) ^ (r&7))) << 4) + (n&7)*2;
    union { __nv_bfloat16 b[2]; uint32_t u; } H, L;
    H.b[0] = __float2bfloat16(v0);
    H.b[1] = __float2bfloat16(v1);
    L.b[0] = __float2bfloat16(v0 - __bfloat162float(H.b[0]));
    L.b[1] = __float2bfloat16(v1 - __bfloat162float(H.b[1]));
    *(uint32_t*)(csm + hOff + off) = H.u;
    *(uint32_t*)(csm + lOff + off) = L.u;
}

__global__ void __launch_bounds__(256, 1) mlp_tc_kernel(
    const float* __restrict__ ray, const float* __restrict__ zbufs,
    const float* __restrict__ W1, const float* __restrict__ b1,
    const float* __restrict__ b2, const float* __restrict__ W3,
    const float* __restrict__ b3, const float* __restrict__ b4)
{
    extern __shared__ char csm[];
    const uint32_t sb = smem_u32(csm);
    const int tid = threadIdx.x, lane = tid & 31, wid = tid >> 5;
    const int mw = wid & 3, nh = wid >> 2;

    for (int i = tid; i < 4096; i += 256) {
        int term = i >> 11, j = i & 2047;
        int n = j >> 4, c = j & 15;
        uint32_t doff = n*256 + (uint32_t)((c ^ (n&7)) << 4);
        uint4 v2 = *(const uint4*)(g_w2m + term*16384 + n*128 + c*8);
        *(uint4*)(csm + MW2H + term*32768 + doff) = v2;
        uint4 v3 = *(const uint4*)(g_w3m + term*16384 + n*128 + c*8);
        *(uint4*)(csm + MW3H + term*32768 + doff) = v3;
        if (n < 32) {
            uint4 v4 = *(const uint4*)(g_w4m + term*4096 + n*128 + c*8);
            *(uint4*)(csm + MW4H + term*8192 + doff) = v4;
        }
    }
    for (int i = tid; i < 128; i += 256) {
        ((float*)(csm+MB1))[i] = b1[i];
        ((float*)(csm+MB2))[i] = b2[i];
        ((float*)(csm+MB3))[i] = b3[i];
    }
    if (tid < 32) ((float*)(csm+MB4))[tid] = b4[tid];
    for (int i = tid; i < 384; i += 256) {
        ((float*)(csm+MW1))[i]  = W1[i];
        ((float*)(csm+MW3D))[i] = W3[16384 + i];
    }
    __syncthreads();

    float* xs = (float*)(csm + MXS);
    const float* b2s = (const float*)(csm + MB2);
    const float* b3s = (const float*)(csm + MB3);
    const float* b4s = (const float*)(csm + MB4);

    for (int t = blockIdx.x; t < 32768; t += gridDim.x) {
        if (tid < 64) {
            int p  = t*64 + tid;
            int yx = p & (HWPIX - 1);
            int k  = p >> 18;
            const float* r = ray + (size_t)yx*7;
            float ox=r[0], oy=r[1], oz=r[2], dx=r[3], dy=r[4], dz=r[5], cs=r[6];
            float z = zbufs[(size_t)yx*8 + k];
            float s = z / cs;
            float* x = xs + tid*8;
            x[0]=ox+dx*s; x[1]=oy+dy*s; x[2]=oz+dz*s;
            x[3]=dx; x[4]=dy; x[5]=dz;
            x[6]=(z>0.f)?1.f:0.f; x[7]=0.f;
        }
        __syncthreads();

        {
            int p = tid & 63, ug = tid >> 6;
            const float* xp = xs + p*8;
            float x0=xp[0], x1=xp[1], x2=xp[2];
            const float* w1s = (const float*)(csm + MW1);
            const float* b1s = (const float*)(csm + MB1);
            float v[8];
#pragma unroll
            for (int q = 0; q < 4; q++) {
#pragma unroll
                for (int j = 0; j < 8; j++) {
                    int u = ug*32 + q*8 + j;
                    v[j] = fmaxf(b1s[u] + x0*w1s[u] + x1*w1s[128+u] + x2*w1s[256+u], 0.f);
                }
                int c = ug*4 + q;
                uint32_t off = p*256 + (uint32_t)((c ^ (p&7)) << 4);
                split_store8((__nv_bfloat16*)(csm + MAH + off),
                             (__nv_bfloat16*)(csm + MAL + off), v);
            }
        }
        __syncthreads();

        {
            float acc[8][4] = {};
            gemm64(sb, MAH, MAL, MW2H, MW2L, mw, nh*64, 4, lane, acc);
            int r0 = mw*16 + (lane>>2);
#pragma unroll
            for (int ns = 0; ns < 8; ns++) {
                int n = nh*64 + ns*8 + (lane&3)*2;
                float bb0 = b2s[n], bb1 = b2s[n+1];
                act_store_pair(csm, MBH, MBL, r0,   n, fmaxf(acc[ns][0]+bb0,0.f), fmaxf(acc[ns][1]+bb1,0.f));
                act_store_pair(csm, MBH, MBL, r0+8, n, fmaxf(acc[ns][2]+bb0,0.f), fmaxf(acc[ns][3]+bb1,0.f));
            }
        }
        __syncthreads();

        {
            float acc[8][4] = {};
            gemm64(sb, MBH, MBL, MW3H, MW3L, mw, nh*64, 4, lane, acc);
            int r0 = mw*16 + (lane>>2);
            const float* w3d = (const float*)(csm + MW3D);
            float dx0 = xs[r0*8+3],     dy0 = xs[r0*8+4],     dz0 = xs[r0*8+5];
            float dx1 = xs[(r0+8)*8+3], dy1 = xs[(r0+8)*8+4], dz1 = xs[(r0+8)*8+5];
#pragma unroll
            for (int ns = 0; ns < 8; ns++) {
                int n = nh*64 + ns*8 + (lane&3)*2;
                float w0a=w3d[n],   w0b=w3d[128+n],   w0c=w3d[256+n];
                float w1a=w3d[n+1], w1b=w3d[128+n+1], w1c=w3d[256+n+1];
                float v0 = fmaxf(acc[ns][0] + b3s[n]   + dx0*w0a + dy0*w0b + dz0*w0c, 0.f);
                float v1 = fmaxf(acc[ns][1] + b3s[n+1] + dx0*w1a + dy0*w1b + dz0*w1c, 0.f);
                float v2 = fmaxf(acc[ns][2] + b3s[n]   + dx1*w0a + dy1*w0b + dz1*w0c, 0.f);
                float v3 = fmaxf(acc[ns][3] + b3s[n+1] + dx1*w1a + dy1*w1b + dz1*w1c, 0.f);
                act_store_pair(csm, MAH, MAL, r0,   n, v0, v1);
                act_store_pair(csm, MAH, MAL, r0+8, n, v2, v3);
            }
        }
        __syncthreads();

        {
            float acc[2][4] = {};
            gemm64(sb, MAH, MAL, MW4H, MW4L, mw, nh*16, 1, lane, acc);
            int r0 = mw*16 + (lane>>2);
#pragma unroll
            for (int ns = 0; ns < 2; ns++) {
                int n = nh*16 + ns*8 + (lane&3)*2;
                float bb0 = b4s[n], bb1 = b4s[n+1];
#pragma unroll
                for (int hh = 0; hh < 2; hh++) {
                    int r = r0 + hh*8;
                    float mk = xs[r*8+6];
                    size_t P = (size_t)t*64 + r;
                    float v0 = (acc[ns][hh*2]   + bb0)*mk;
                    float v1 = (acc[ns][hh*2+1] + bb1)*mk;
                    union { __nv_bfloat16 b[2]; uint32_t u; } H, L;
                    H.b[0] = __float2bfloat16(v0);
                    H.b[1] = __float2bfloat16(v1);
                    L.b[0] = __float2bfloat16(v0 - __bfloat162float(H.b[0]));
                    L.b[1] = __float2bfloat16(v1 - __bfloat162float(H.b[1]));
                    *(uint32_t*)(g_ah + P*64 + n) = H.u;
                    *(uint32_t*)(g_al + P*64 + n) = L.u;
                }
            }
        }
        __syncthreads();
    }
}

// ======================= sup1: 3 -> 32 relu, split-store padded to 64ch ========
__global__ void sup1_kernel(const float* __restrict__ colors,
                            const float* __restrict__ kw, const float* __restrict__ bw)
{
    __shared__ float wgt[864];
    int tx = threadIdx.x, ty = threadIdx.y, tid = ty*32 + tx;
    for (int i = tid; i < 864; i += 256) wgt[i] = kw[i];
    __syncthreads();
    int x = blockIdx.x*32 + tx, y = blockIdx.y*8 + ty, k = blockIdx.z;
    float4 acc[8];
#pragma unroll
    for (int j = 0; j < 8; j++) acc[j] = ((const float4*)bw)[j];
    for (int dy = 0; dy < 3; dy++)
    for (int dx = 0; dx < 3; dx++) {
        int iy = y + dy - 1, ix = x + dx - 1;
        if (iy < 0 || iy >= HH || ix < 0 || ix >= WW) continue;
        const float* cp = colors + ((size_t)iy*WW + ix)*24 + k*3;
        const float* wr = wgt + (dy*3 + dx)*96;
#pragma unroll
        for (int ic = 0; ic < 3; ic++) {
            float v = cp[ic];
            const float4* w4 = (const float4*)(wr + ic*32);
#pragma unroll
            for (int j = 0; j < 8; j++) {
                float4 w = w4[j];
                acc[j].x=fmaf(v,w.x,acc[j].x); acc[j].y=fmaf(v,w.y,acc[j].y);
                acc[j].z=fmaf(v,w.z,acc[j].z); acc[j].w=fmaf(v,w.w,acc[j].w);
            }
        }
    }
    size_t pix = (size_t)k*HWPIX + (size_t)y*WW + x;
    float v[32];
#pragma unroll
    for (int j = 0; j < 8; j++) {
        v[j*4]  =fmaxf(acc[j].x,0.f); v[j*4+1]=fmaxf(acc[j].y,0.f);
        v[j*4+2]=fmaxf(acc[j].z,0.f); v[j*4+3]=fmaxf(acc[j].w,0.f);
    }
#pragma unroll
    for (int q = 0; q < 4; q++)
        split_store8(g_bh + pix*64 + q*8, g_bl + pix*64 + q*8, v + q*8);
    uint4 z = make_uint4(0,0,0,0);
#pragma unroll
    for (int q = 0; q < 4; q++) {
        ((uint4*)(g_bh + pix*64 + 32))[q] = z;
        ((uint4*)(g_bl + pix*64 + 32))[q] = z;
    }
}

// ======================= conv weight preps =======================
__global__ void wprep_kernel(const float* __restrict__ kw, int which)
{
    int idx = blockIdx.x*256 + threadIdx.x;
    if (idx >= 73728) return;
    int t = idx / 36864, r = idx % 36864;
    int p = r >> 12, q = r & 4095;
    int oc = q >> 6, ic = q & 63;
    float w = kw[((size_t)p*64 + ic)*64 + oc];
    __nv_bfloat16 hb = __float2bfloat16(w);
    __nv_bfloat16 o = t ? __float2bfloat16(w - __bfloat162float(hb)) : hb;
    (which ? g_w2t : g_w1t)[idx] = o;
}

__global__ void wprep_sup2_kernel(const float* __restrict__ kw)
{
    int idx = blockIdx.x*256 + threadIdx.x;
    if (idx >= 36864) return;
    int t = idx / 18432, r = idx % 18432;
    int tap = r >> 11, q = r & 2047;
    int oc = q >> 6, ic = q & 63;
    float w = (ic < 32) ? kw[((size_t)tap*32 + ic)*32 + oc] : 0.f;
    __nv_bfloat16 hb = __float2bfloat16(w);
    g_wst[idx] = t ? __float2bfloat16(w - __bfloat162float(hb)) : hb;
}

// ===== mma.sync 64->64 3x3 conv, 512 threads (MODE 0: mpn1+relu, 1: mpn2+fuse) =====
#define PITCH 136
#define WOFF 52224
#define BOFF (WOFF + 147456)
#define CONV_SMEM (BOFF + 256)

template<int MODE>
__global__ void __launch_bounds__(512, 1) conv64_kernel(const float* __restrict__ bias)
{
    extern __shared__ char csm[];
    const uint32_t sb = smem_u32(csm);
    const int tid = threadIdx.x, wid = tid >> 5, lane = tid & 31;
    const int mw = wid & 7, nh = wid >> 3;      // 8 pixel-groups x 2 N-halves
    const int y = blockIdx.x, k = blockIdx.y;
    const int g = lane >> 2, tg = lane & 3;

    {
        const __nv_bfloat16* ws = MODE ? g_w2t : g_w1t;
        for (int i = tid; i < 9216; i += 512) {
            uint4 v = *(const uint4*)(ws + i*8);
            *(uint4*)(csm + WOFF + SWZ(i*16)) = v;
        }
    }
    if (tid < 64) ((float*)(csm + BOFF))[tid] = bias[tid];

    const __nv_bfloat16* srcH = MODE ? g_bh : g_ah;
    const __nv_bfloat16* srcL = MODE ? g_bl : g_al;
    float* bs = (float*)(csm + BOFF);

    const uint32_t alane = (mw*16 + (lane & 15))*128 + (lane >> 4)*16;
    const uint32_t blane = ((lane & 7) + ((lane & 16) >> 1))*128 + (lane & 8)*2;

    for (int t = 0; t < 4; t++) {
        const int x0 = t*128;
        float acc[4][4];
#pragma unroll
        for (int s = 0; s < 4; s++)
#pragma unroll
            for (int j = 0; j < 4; j++) acc[s][j] = 0.f;

        for (int pass = 0; pass < 2; pass++) {
            const __nv_bfloat16* src = pass ? srcL : srcH;
            __syncthreads();
            for (int idx = tid; idx < 3120; idx += 512) {
                int r = idx >> 3, c = idx & 7;
                int dy = r/130, sx = r - dy*130;
                int iy = y + dy - 1, ix = x0 + sx - 1;
                uint4 v = make_uint4(0,0,0,0);
                if (iy >= 0 && iy < HH && (unsigned)ix < WW)
                    v = *(const uint4*)(src + ((size_t)k*HWPIX + (size_t)iy*WW + ix)*64 + c*8);
                *(uint4*)(csm + SWZ((dy*PITCH + sx)*128 + c*16)) = v;
            }
            __syncthreads();

            const int nterm = pass ? 1 : 2;
            for (int tap = 0; tap < 9; tap++) {
                int dy = tap/3, dxo = tap - dy*3;
                uint32_t abase = (dy*PITCH + dxo)*128 + alane;
#pragma unroll
                for (int kc = 0; kc < 4; kc++) {
                    uint32_t a0,a1,a2,a3;
                    LDSM4(a0,a1,a2,a3, sb + SWZ(abase + kc*32));
                    for (int tm = 0; tm < nterm; tm++) {
                        uint32_t wb = sb + WOFF + tm*73728;
#pragma unroll
                        for (int ns = 0; ns < 2; ns++) {
                            uint32_t b0,b1,b2,b3;
                            LDSM4(b0,b1,b2,b3, wb + SWZ(tap*8192 + (nh*2+ns)*2048 + kc*32 + blane));
                            MMA16816(acc[ns*2],   a0,a1,a2,a3, b0,b1);
                            MMA16816(acc[ns*2+1], a0,a1,a2,a3, b2,b3);
                        }
                    }
                }
            }
        }

        if (MODE == 0) {
#pragma unroll
            for (int s = 0; s < 4; s++) {
                int oc = nh*32 + s*8 + tg*2;
                float b0v = bs[oc], b1v = bs[oc+1];
#pragma unroll
                for (int half = 0; half < 2; half++) {
                    int px = mw*16 + g + half*8;
                    int gx = x0 + px;
                    size_t pix = (size_t)k*HWPIX + (size_t)y*WW + gx;
                    float v0 = fmaxf(acc[s][half*2]   + b0v, 0.f);
                    float v1 = fmaxf(acc[s][half*2+1] + b1v, 0.f);
                    union { __nv_bfloat16 b[2]; uint32_t u; } H, L;
                    H.b[0] = __float2bfloat16(v0);
                    H.b[1] = __float2bfloat16(v1);
                    L.b[0] = __float2bfloat16(v0 - __bfloat162float(H.b[0]));
                    L.b[1] = __float2bfloat16(v1 - __bfloat162float(H.b[1]));
                    *(uint32_t*)(g_bh + pix*64 + oc) = H.u;
                    *(uint32_t*)(g_bl + pix*64 + oc) = L.u;
                }
            }
        } else {
            float* fsm = (float*)csm;
            __syncthreads();
#pragma unroll
            for (int s = 0; s < 4; s++) {
                int oc = nh*32 + s*8 + tg*2;
#pragma unroll
                for (int half = 0; half < 2; half++) {
                    int px = mw*16 + g + half*8;
                    fsm[px*68 + oc]     = acc[s][half*2]   + bs[oc];
                    fsm[px*68 + oc + 1] = acc[s][half*2+1] + bs[oc+1];
                }
            }
            __syncthreads();
            if (tid < 128) {
                int gx = x0 + tid;
                size_t pix = (size_t)k*HWPIX + (size_t)y*WW + gx;
                const uint4* ah4 = (const uint4*)(g_ah + pix*64);
                const uint4* al4 = (const uint4*)(g_al + pix*64);
                float alpha = 1.f, fuse = 0.f;
#pragma unroll
                for (int q = 0; q < 8; q++) {
                    union { uint4 u; __nv_bfloat16 b[8]; } Ha, La;
                    Ha.u = ah4[q]; La.u = al4[q];
#pragma unroll
                    for (int j = 0; j < 8; j++) {
                        float a = fsm[tid*68 + q*8 + j];
                        float m = 1.f/(1.f + expf(-a));
                        float f = __bfloat162float(Ha.b[j]) + __bfloat162float(La.b[j]);
                        fuse += f*m*alpha;
                        alpha *= (1.f - m);
                    }
                }
                g_fuse[((size_t)y*WW + gx)*8 + k] = fuse;
            }
            __syncthreads();
        }
    }
}

// ===== sup2 tensor conv, 512 threads: 32 -> 32 (ic padded to 64), no relu =====
#define W2OFF 52224
#define B2OFF (W2OFF + 73728)
#define SUP2_SMEM (B2OFF + 128)

__global__ void __launch_bounds__(512, 1) sup2_tc_kernel(const float* __restrict__ bias)
{
    extern __shared__ char csm[];
    const uint32_t sb = smem_u32(csm);
    const int tid = threadIdx.x, wid = tid >> 5, lane = tid & 31;
    const int mw = wid & 7, nh = wid >> 3;
    const int y = blockIdx.x, k = blockIdx.y;
    const int g = lane >> 2, tg = lane & 3;

    for (int i = tid; i < 4608; i += 512) {
        uint4 v = *(const uint4*)(g_wst + i*8);
        *(uint4*)(csm + W2OFF + SWZ(i*16)) = v;
    }
    if (tid < 32) ((float*)(csm + B2OFF))[tid] = bias[tid];
    float* bs = (float*)(csm + B2OFF);

    const uint32_t alane = (mw*16 + (lane & 15))*128 + (lane >> 4)*16;
    const uint32_t blane = ((lane & 7) + ((lane & 16) >> 1))*128 + (lane & 8)*2;

    for (int t = 0; t < 4; t++) {
        const int x0 = t*128;
        float acc[2][4];
#pragma unroll
        for (int s = 0; s < 2; s++)
#pragma unroll
            for (int j = 0; j < 4; j++) acc[s][j] = 0.f;

        for (int pass = 0; pass < 2; pass++) {
            const __nv_bfloat16* src = pass ? g_bl : g_bh;
            __syncthreads();
            for (int idx = tid; idx < 1560; idx += 512) {
                int r = idx >> 2, c = idx & 3;
                int dy = r/130, sx = r - dy*130;
                int iy = y + dy - 1, ix = x0 + sx - 1;
                uint4 v = make_uint4(0,0,0,0);
                if (iy >= 0 && iy < HH && (unsigned)ix < WW)
                    v = *(const uint4*)(src + ((size_t)k*HWPIX + (size_t)iy*WW + ix)*64 + c*8);
                *(uint4*)(csm + SWZ((dy*PITCH + sx)*128 + c*16)) = v;
            }
            __syncthreads();

            const int nterm = pass ? 1 : 2;
            for (int tap = 0; tap < 9; tap++) {
                int dy = tap/3, dxo = tap - dy*3;
                uint32_t abase = (dy*PITCH + dxo)*128 + alane;
#pragma unroll
                for (int kc = 0; kc < 2; kc++) {
                    uint32_t a0,a1,a2,a3;
                    LDSM4(a0,a1,a2,a3, sb + SWZ(abase + kc*32));
                    for (int tm = 0; tm < nterm; tm++) {
                        uint32_t wb = sb + W2OFF + tm*36864;
                        uint32_t b0,b1,b2,b3;
                        LDSM4(b0,b1,b2,b3, wb + SWZ(tap*4096 + nh*2048 + kc*32 + blane));
                        MMA16816(acc[0], a0,a1,a2,a3, b0,b1);
                        MMA16816(acc[1], a0,a1,a2,a3, b2,b3);
                    }
                }
            }
        }

#pragma unroll
        for (int s = 0; s < 2; s++) {
            int oc = nh*16 + s*8 + tg*2;
            float b0v = bs[oc], b1v = bs[oc+1];
#pragma unroll
            for (int half = 0; half < 2; half++) {
                int px = mw*16 + g + half*8;
                int gx = x0 + px;
                size_t pix = (size_t)k*HWPIX + (size_t)y*WW + gx;
                float v0 = acc[s][half*2]   + b0v;
                float v1 = acc[s][half*2+1] + b1v;
                union { __nv_bfloat16 b[2]; uint32_t u; } H, L;
                H.b[0] = __float2bfloat16(v0);
                H.b[1] = __float2bfloat16(v1);
                L.b[0] = __float2bfloat16(v0 - __bfloat162float(H.b[0]));
                L.b[1] = __float2bfloat16(v1 - __bfloat162float(H.b[1]));
                *(uint32_t*)(g_ah + pix*64 + 32 + oc) = H.u;
                *(uint32_t*)(g_al + pix*64 + 32 + oc) = L.u;
            }
        }
    }
}

// ======================= un1: 8 -> 32 relu =======================
__global__ void un1_kernel(const float* __restrict__ kw, const float* __restrict__ bw)
{
    __shared__ float wgt[2304];
    int tx = threadIdx.x, ty = threadIdx.y, tid = ty*32 + tx;
    for (int i = tid; i < 2304; i += 256) wgt[i] = kw[i];
    __syncthreads();
    int x = blockIdx.x*32 + tx, y = blockIdx.y*8 + ty;
    float4 acc[8];
#pragma unroll
    for (int j = 0; j < 8; j++) acc[j] = ((const float4*)bw)[j];
    for (int dy = 0; dy < 3; dy++)
    for (int dx = 0; dx < 3; dx++) {
        int iy = y + dy - 1, ix = x + dx - 1;
        if (iy < 0 || iy >= HH || ix < 0 || ix >= WW) continue;
        const float* fp = g_fuse + ((size_t)iy*WW + ix)*8;
        float4 f0 = ((const float4*)fp)[0];
        float4 f1 = ((const float4*)fp)[1];
        float fv[8] = {f0.x,f0.y,f0.z,f0.w,f1.x,f1.y,f1.z,f1.w};
        const float* wr = wgt + (dy*3 + dx)*256;
#pragma unroll
        for (int ic = 0; ic < 8; ic++) {
            float v = fv[ic];
            const float4* w4 = (const float4*)(wr + ic*32);
#pragma unroll
            for (int j = 0; j < 8; j++) {
                float4 w = w4[j];
                acc[j].x=fmaf(v,w.x,acc[j].x); acc[j].y=fmaf(v,w.y,acc[j].y);
                acc[j].z=fmaf(v,w.z,acc[j].z); acc[j].w=fmaf(v,w.w,acc[j].w);
            }
        }
    }
    float* dst = g_u32 + ((size_t)y*WW + x)*32;
#pragma unroll
    for (int j = 0; j < 8; j++) {
        float4 o;
        o.x=fmaxf(acc[j].x,0.f); o.y=fmaxf(acc[j].y,0.f);
        o.z=fmaxf(acc[j].z,0.f); o.w=fmaxf(acc[j].w,0.f);
        ((float4*)dst)[j] = o;
    }
}

// ======================= un2: 32 -> 3 =======================
__global__ void un2_kernel(const float* __restrict__ kw, const float* __restrict__ bw,
                           float* __restrict__ out)
{
    __shared__ float wgt[864];
    int tx = threadIdx.x, ty = threadIdx.y, tid = ty*32 + tx;
    for (int i = tid; i < 864; i += 256) wgt[i] = kw[i];
    __syncthreads();
    int x = blockIdx.x*32 + tx, y = blockIdx.y*8 + ty;
    float a0 = bw[0], a1 = bw[1], a2 = bw[2];
    for (int dy = 0; dy < 3; dy++)
    for (int dx = 0; dx < 3; dx++) {
        int iy = y + dy - 1, ix = x + dx - 1;
        if (iy < 0 || iy >= HH || ix < 0 || ix >= WW) continue;
        const float* up = g_u32 + ((size_t)iy*WW + ix)*32;
        const float* wr = wgt + (dy*3 + dx)*96;
#pragma unroll
        for (int ic4 = 0; ic4 < 8; ic4++) {
            float4 v = ((const float4*)up)[ic4];
            float vv[4] = {v.x, v.y, v.z, v.w};
#pragma unroll
            for (int j = 0; j < 4; j++) {
                int ic = ic4*4 + j;
                a0 = fmaf(vv[j], wr[ic*3 + 0], a0);
                a1 = fmaf(vv[j], wr[ic*3 + 1], a1);
                a2 = fmaf(vv[j], wr[ic*3 + 2], a2);
            }
        }
    }
    float* dst = out + ((size_t)y*WW + x)*3;
    dst[0]=a0; dst[1]=a1; dst[2]=a2;
}

// ======================= launch =======================
extern "C" void kernel_launch(void* const* d_in, const int* in_sizes, int n_in,
                              void* d_out, int out_size)
{
    const float* colors = (const float*)d_in[0];
    const float* ray    = (const float*)d_in[1];
    const float* zbufs  = (const float*)d_in[2];
    const float* W1 = (const float*)d_in[3];  const float* b1 = (const float*)d_in[4];
    const float* W2 = (const float*)d_in[5];  const float* b2 = (const float*)d_in[6];
    const float* W3 = (const float*)d_in[7];  const float* b3 = (const float*)d_in[8];
    const float* W4 = (const float*)d_in[9];  const float* b4 = (const float*)d_in[10];
    const float* k_sup1 = (const float*)d_in[11]; const float* b_sup1 = (const float*)d_in[12];
    const float* k_sup2 = (const float*)d_in[13]; const float* b_sup2 = (const float*)d_in[14];
    const float* k_mpn1 = (const float*)d_in[15]; const float* b_mpn1 = (const float*)d_in[16];
    const float* k_mpn2 = (const float*)d_in[17]; const float* b_mpn2 = (const float*)d_in[18];
    const float* k_un1  = (const float*)d_in[19]; const float* b_un1  = (const float*)d_in[20];
    const float* k_un2  = (const float*)d_in[21]; const float* b_un2  = (const float*)d_in[22];
    float* out = (float*)d_out;

    static cudaStream_t sB = nullptr;
    static cudaEvent_t evRoot = nullptr, evB = nullptr;
    if (sB == nullptr) {
        cudaStreamCreateWithFlags(&sB, cudaStreamNonBlocking);
        cudaEventCreateWithFlags(&evRoot, cudaEventDisableTiming);
        cudaEventCreateWithFlags(&evB, cudaEventDisableTiming);
    }

    cudaFuncSetAttribute(mlp_tc_kernel, cudaFuncAttributeMaxDynamicSharedMemorySize, MLP_TC_SMEM);
    cudaFuncSetAttribute(sup2_tc_kernel, cudaFuncAttributeMaxDynamicSharedMemorySize, SUP2_SMEM);
    cudaFuncSetAttribute(conv64_kernel<0>, cudaFuncAttributeMaxDynamicSharedMemorySize, CONV_SMEM);
    cudaFuncSetAttribute(conv64_kernel<1>, cudaFuncAttributeMaxDynamicSharedMemorySize, CONV_SMEM);

    // fork: stream B handles conv-weight preps + sup chain, overlapping the MLP
    cudaEventRecord(evRoot, 0);
    cudaStreamWaitEvent(sB, evRoot, 0);

    mlpprep_kernel<<<144, 256>>>(W2, W3, W4);
    mlp_tc_kernel<<<148, 256, MLP_TC_SMEM>>>(ray, zbufs, W1, b1, b2, W3, b3, b4);

    wprep_kernel<<<288, 256, 0, sB>>>(k_mpn1, 0);
    wprep_kernel<<<288, 256, 0, sB>>>(k_mpn2, 1);
    wprep_sup2_kernel<<<144, 256, 0, sB>>>(k_sup2);
    sup1_kernel<<<dim3(16,64,8), dim3(32,8), 0, sB>>>(colors, k_sup1, b_sup1);
    sup2_tc_kernel<<<dim3(512,8), 512, SUP2_SMEM, sB>>>(b_sup2);

    cudaEventRecord(evB, sB);
    cudaStreamWaitEvent(0, evB, 0);

    conv64_kernel<0><<<dim3(512,8), 512, CONV_SMEM>>>(b_mpn1);
    conv64_kernel<1><<<dim3(512,8), 512, CONV_SMEM>>>(b_mpn2);
    un1_kernel<<<dim3(16,64), dim3(32,8)>>>(k_un1, b_un1);
    un2_kernel<<<dim3(16,64), dim3(32,8)>>>(k_un2, b_un2, out);
}

// round 10
// speedup vs baseline: 3.5000x; 1.2253x over previous
#include <cuda_runtime.h>
#include <cuda_bf16.h>
#include <cstdint>
#include <math.h>

#define HH 512
#define WW 512
#define HWPIX (HH*WW)

// ---------------- scratch (device globals) ----------------
__device__ __nv_bfloat16 g_ah[134217728];  // [8][H][W][64] fm hi
__device__ __nv_bfloat16 g_al[134217728];  // fm lo
__device__ __nv_bfloat16 g_bh[134217728];  // sup1 out, later relu(mpn1) hi
__device__ __nv_bfloat16 g_bl[134217728];  // lo
__device__ float g_fuse[2097152];          // [H][W][8]
__device__ float g_u32[8388608];           // [H][W][32]
__device__ __nv_bfloat16 g_w1t[73728];     // conv mpn1 [2][9][64][64]
__device__ __nv_bfloat16 g_w2t[73728];     // conv mpn2
__device__ __nv_bfloat16 g_wst[36864];     // conv sup2 [2][9][32][64] (ic padded)
__device__ __nv_bfloat16 g_w2m[32768];     // mlp W2 [2][128][128] (n,k)
__device__ __nv_bfloat16 g_w3m[32768];     // mlp W3 rows 0..127
__device__ __nv_bfloat16 g_w4m[8192];      // mlp W4 [2][32][128]

#define SWZ(off) ((off) ^ (((off) >> 3) & 0x70))

__device__ __forceinline__ uint32_t smem_u32(const void* p) {
    uint32_t a;
    asm("{ .reg .u64 t; cvta.to.shared.u64 t, %1; cvt.u32.u64 %0, t; }" : "=r"(a) : "l"(p));
    return a;
}
#define LDSM4(r0,r1,r2,r3,addr) \
    asm volatile("ldmatrix.sync.aligned.m8n8.x4.shared.b16 {%0,%1,%2,%3}, [%4];" \
        : "=r"(r0), "=r"(r1), "=r"(r2), "=r"(r3) : "r"(addr))
#define MMA16816(c,a0,a1,a2,a3,b0,b1) \
    asm volatile("mma.sync.aligned.m16n8k16.row.col.f32.bf16.bf16.f32 " \
        "{%0,%1,%2,%3},{%4,%5,%6,%7},{%8,%9},{%0,%1,%2,%3};" \
        : "+f"((c)[0]), "+f"((c)[1]), "+f"((c)[2]), "+f"((c)[3]) \
        : "r"(a0), "r"(a1), "r"(a2), "r"(a3), "r"(b0), "r"(b1))

__device__ __forceinline__ void split_store8(__nv_bfloat16* dh, __nv_bfloat16* dl, const float* v) {
    union { __nv_bfloat16 b[8]; uint4 u; } Hh, Ll;
#pragma unroll
    for (int j = 0; j < 8; j++) {
        __nv_bfloat16 hb = __float2bfloat16(v[j]);
        Hh.b[j] = hb;
        Ll.b[j] = __float2bfloat16(v[j] - __bfloat162float(hb));
    }
    *(uint4*)dh = Hh.u; *(uint4*)dl = Ll.u;
}

// ======================= MLP weight prep (transpose + split) =======================
__global__ void mlpprep_kernel(const float* __restrict__ W2, const float* __restrict__ W3,
                               const float* __restrict__ W4)
{
    int idx = blockIdx.x*256 + threadIdx.x;
    if (idx >= 36864) return;
    if (idx < 16384) {
        int n = idx >> 7, k = idx & 127;
        float w = W2[k*128 + n];
        __nv_bfloat16 hb = __float2bfloat16(w);
        g_w2m[idx] = hb;
        g_w2m[16384 + idx] = __float2bfloat16(w - __bfloat162float(hb));
    } else if (idx < 32768) {
        int j = idx - 16384;
        int n = j >> 7, k = j & 127;
        float w = W3[k*128 + n];
        __nv_bfloat16 hb = __float2bfloat16(w);
        g_w3m[j] = hb;
        g_w3m[16384 + j] = __float2bfloat16(w - __bfloat162float(hb));
    } else {
        int j = idx - 32768;
        int n = j >> 7, k = j & 127;
        float w = W4[k*32 + n];
        __nv_bfloat16 hb = __float2bfloat16(w);
        g_w4m[j] = hb;
        g_w4m[4096 + j] = __float2bfloat16(w - __bfloat162float(hb));
    }
}

// ======================= tensor MLP =======================
#define MW2H 0
#define MW2L 32768
#define MW3H 65536
#define MW3L 98304
#define MW4H 131072
#define MW4L 139264
#define MAH  147456
#define MAL  163840
#define MBH  180224
#define MBL  196608
#define MXS  212992
#define MW3D 215040
#define MB1  216576
#define MB2  217088
#define MB3  217600
#define MB4  218112
#define MW1  218240
#define MLP_TC_SMEM 219776

__device__ __forceinline__ void gemm64(uint32_t sb, int ahOff, int alOff, int whOff, int wlOff,
                                       int mw, int nbase, int npairs, int lane, float (*acc)[4])
{
    const int ar = mw*16 + (lane & 15);
    const uint32_t aRow = sb + ar*256;
    const int arx = ar & 7;
    const int brl = (lane & 7) + ((lane & 16) >> 1);
    const int cbk = (lane & 8) >> 3;
#pragma unroll
    for (int kc = 0; kc < 8; kc++) {
        int ca = kc*2 + (lane >> 4);
        uint32_t aoff = (uint32_t)((ca ^ arx) << 4);
        uint32_t ah0,ah1,ah2,ah3, al0,al1,al2,al3;
        LDSM4(ah0,ah1,ah2,ah3, aRow + ahOff + aoff);
        LDSM4(al0,al1,al2,al3, aRow + alOff + aoff);
#pragma unroll
        for (int ns = 0; ns < npairs; ns++) {
            int br = nbase + ns*16 + brl;
            int cb = kc*2 + cbk;
            uint32_t boff = br*256 + (uint32_t)(((cb ^ (br & 7))) << 4);
            uint32_t b0,b1,b2,b3;
            LDSM4(b0,b1,b2,b3, sb + whOff + boff);
            MMA16816(acc[ns*2],   ah0,ah1,ah2,ah3, b0,b1);
            MMA16816(acc[ns*2+1], ah0,ah1,ah2,ah3, b2,b3);
            MMA16816(acc[ns*2],   al0,al1,al2,al3, b0,b1);
            MMA16816(acc[ns*2+1], al0,al1,al2,al3, b2,b3);
            LDSM4(b0,b1,b2,b3, sb + wlOff + boff);
            MMA16816(acc[ns*2],   ah0,ah1,ah2,ah3, b0,b1);
            MMA16816(acc[ns*2+1], ah0,ah1,ah2,ah3, b2,b3);
        }
    }
}

__device__ __forceinline__ void act_store_pair(char* csm, int hOff, int lOff,
                                               int r, int n, float v0, float v1)
{
    uint32_t off = r*256 + (uint32_t)((((n>>3) ^ (r&7))) << 4) + (n&7)*2;
    union { __nv_bfloat16 b[2]; uint32_t u; } H, L;
    H.b[0] = __float2bfloat16(v0);
    H.b[1] = __float2bfloat16(v1);
    L.b[0] = __float2bfloat16(v0 - __bfloat162float(H.b[0]));
    L.b[1] = __float2bfloat16(v1 - __bfloat162float(H.b[1]));
    *(uint32_t*)(csm + hOff + off) = H.u;
    *(uint32_t*)(csm + lOff + off) = L.u;
}

__global__ void __launch_bounds__(256, 1) mlp_tc_kernel(
    const float* __restrict__ ray, const float* __restrict__ zbufs,
    const float* __restrict__ W1, const float* __restrict__ b1,
    const float* __restrict__ b2, const float* __restrict__ W3,
    const float* __restrict__ b3, const float* __restrict__ b4)
{
    extern __shared__ char csm[];
    const uint32_t sb = smem_u32(csm);
    const int tid = threadIdx.x, lane = tid & 31, wid = tid >> 5;
    const int mw = wid & 3, nh = wid >> 2;

    for (int i = tid; i < 4096; i += 256) {
        int term = i >> 11, j = i & 2047;
        int n = j >> 4, c = j & 15;
        uint32_t doff = n*256 + (uint32_t)((c ^ (n&7)) << 4);
        uint4 v2 = *(const uint4*)(g_w2m + term*16384 + n*128 + c*8);
        *(uint4*)(csm + MW2H + term*32768 + doff) = v2;
        uint4 v3 = *(const uint4*)(g_w3m + term*16384 + n*128 + c*8);
        *(uint4*)(csm + MW3H + term*32768 + doff) = v3;
        if (n < 32) {
            uint4 v4 = *(const uint4*)(g_w4m + term*4096 + n*128 + c*8);
            *(uint4*)(csm + MW4H + term*8192 + doff) = v4;
        }
    }
    for (int i = tid; i < 128; i += 256) {
        ((float*)(csm+MB1))[i] = b1[i];
        ((float*)(csm+MB2))[i] = b2[i];
        ((float*)(csm+MB3))[i] = b3[i];
    }
    if (tid < 32) ((float*)(csm+MB4))[tid] = b4[tid];
    for (int i = tid; i < 384; i += 256) {
        ((float*)(csm+MW1))[i]  = W1[i];
        ((float*)(csm+MW3D))[i] = W3[16384 + i];
    }
    __syncthreads();

    float* xs = (float*)(csm + MXS);
    const float* b2s = (const float*)(csm + MB2);
    const float* b3s = (const float*)(csm + MB3);
    const float* b4s = (const float*)(csm + MB4);

    for (int t = blockIdx.x; t < 32768; t += gridDim.x) {
        if (tid < 64) {
            int p  = t*64 + tid;
            int yx = p & (HWPIX - 1);
            int k  = p >> 18;
            const float* r = ray + (size_t)yx*7;
            float ox=r[0], oy=r[1], oz=r[2], dx=r[3], dy=r[4], dz=r[5], cs=r[6];
            float z = zbufs[(size_t)yx*8 + k];
            float s = z / cs;
            float* x = xs + tid*8;
            x[0]=ox+dx*s; x[1]=oy+dy*s; x[2]=oz+dz*s;
            x[3]=dx; x[4]=dy; x[5]=dz;
            x[6]=(z>0.f)?1.f:0.f; x[7]=0.f;
        }
        __syncthreads();

        {
            int p = tid & 63, ug = tid >> 6;
            const float* xp = xs + p*8;
            float x0=xp[0], x1=xp[1], x2=xp[2];
            const float* w1s = (const float*)(csm + MW1);
            const float* b1s = (const float*)(csm + MB1);
            float v[8];
#pragma unroll
            for (int q = 0; q < 4; q++) {
#pragma unroll
                for (int j = 0; j < 8; j++) {
                    int u = ug*32 + q*8 + j;
                    v[j] = fmaxf(b1s[u] + x0*w1s[u] + x1*w1s[128+u] + x2*w1s[256+u], 0.f);
                }
                int c = ug*4 + q;
                uint32_t off = p*256 + (uint32_t)((c ^ (p&7)) << 4);
                split_store8((__nv_bfloat16*)(csm + MAH + off),
                             (__nv_bfloat16*)(csm + MAL + off), v);
            }
        }
        __syncthreads();

        {
            float acc[8][4] = {};
            gemm64(sb, MAH, MAL, MW2H, MW2L, mw, nh*64, 4, lane, acc);
            int r0 = mw*16 + (lane>>2);
#pragma unroll
            for (int ns = 0; ns < 8; ns++) {
                int n = nh*64 + ns*8 + (lane&3)*2;
                float bb0 = b2s[n], bb1 = b2s[n+1];
                act_store_pair(csm, MBH, MBL, r0,   n, fmaxf(acc[ns][0]+bb0,0.f), fmaxf(acc[ns][1]+bb1,0.f));
                act_store_pair(csm, MBH, MBL, r0+8, n, fmaxf(acc[ns][2]+bb0,0.f), fmaxf(acc[ns][3]+bb1,0.f));
            }
        }
        __syncthreads();

        {
            float acc[8][4] = {};
            gemm64(sb, MBH, MBL, MW3H, MW3L, mw, nh*64, 4, lane, acc);
            int r0 = mw*16 + (lane>>2);
            const float* w3d = (const float*)(csm + MW3D);
            float dx0 = xs[r0*8+3],     dy0 = xs[r0*8+4],     dz0 = xs[r0*8+5];
            float dx1 = xs[(r0+8)*8+3], dy1 = xs[(r0+8)*8+4], dz1 = xs[(r0+8)*8+5];
#pragma unroll
            for (int ns = 0; ns < 8; ns++) {
                int n = nh*64 + ns*8 + (lane&3)*2;
                float w0a=w3d[n],   w0b=w3d[128+n],   w0c=w3d[256+n];
                float w1a=w3d[n+1], w1b=w3d[128+n+1], w1c=w3d[256+n+1];
                float v0 = fmaxf(acc[ns][0] + b3s[n]   + dx0*w0a + dy0*w0b + dz0*w0c, 0.f);
                float v1 = fmaxf(acc[ns][1] + b3s[n+1] + dx0*w1a + dy0*w1b + dz0*w1c, 0.f);
                float v2 = fmaxf(acc[ns][2] + b3s[n]   + dx1*w0a + dy1*w0b + dz1*w0c, 0.f);
                float v3 = fmaxf(acc[ns][3] + b3s[n+1] + dx1*w1a + dy1*w1b + dz1*w1c, 0.f);
                act_store_pair(csm, MAH, MAL, r0,   n, v0, v1);
                act_store_pair(csm, MAH, MAL, r0+8, n, v2, v3);
            }
        }
        __syncthreads();

        {
            float acc[2][4] = {};
            gemm64(sb, MAH, MAL, MW4H, MW4L, mw, nh*16, 1, lane, acc);
            int r0 = mw*16 + (lane>>2);
#pragma unroll
            for (int ns = 0; ns < 2; ns++) {
                int n = nh*16 + ns*8 + (lane&3)*2;
                float bb0 = b4s[n], bb1 = b4s[n+1];
#pragma unroll
                for (int hh = 0; hh < 2; hh++) {
                    int r = r0 + hh*8;
                    float mk = xs[r*8+6];
                    size_t P = (size_t)t*64 + r;
                    float v0 = (acc[ns][hh*2]   + bb0)*mk;
                    float v1 = (acc[ns][hh*2+1] + bb1)*mk;
                    union { __nv_bfloat16 b[2]; uint32_t u; } H, L;
                    H.b[0] = __float2bfloat16(v0);
                    H.b[1] = __float2bfloat16(v1);
                    L.b[0] = __float2bfloat16(v0 - __bfloat162float(H.b[0]));
                    L.b[1] = __float2bfloat16(v1 - __bfloat162float(H.b[1]));
                    *(uint32_t*)(g_ah + P*64 + n) = H.u;
                    *(uint32_t*)(g_al + P*64 + n) = L.u;
                }
            }
        }
        __syncthreads();
    }
}

// ======================= sup1: 3 -> 32 relu, split-store (ch 0..31 only) ========
__global__ void sup1_kernel(const float* __restrict__ colors,
                            const float* __restrict__ kw, const float* __restrict__ bw)
{
    __shared__ float wgt[864];
    int tx = threadIdx.x, ty = threadIdx.y, tid = ty*32 + tx;
    for (int i = tid; i < 864; i += 256) wgt[i] = kw[i];
    __syncthreads();
    int x = blockIdx.x*32 + tx, y = blockIdx.y*8 + ty, k = blockIdx.z;
    float4 acc[8];
#pragma unroll
    for (int j = 0; j < 8; j++) acc[j] = ((const float4*)bw)[j];
    for (int dy = 0; dy < 3; dy++)
    for (int dx = 0; dx < 3; dx++) {
        int iy = y + dy - 1, ix = x + dx - 1;
        if (iy < 0 || iy >= HH || ix < 0 || ix >= WW) continue;
        const float* cp = colors + ((size_t)iy*WW + ix)*24 + k*3;
        const float* wr = wgt + (dy*3 + dx)*96;
#pragma unroll
        for (int ic = 0; ic < 3; ic++) {
            float v = cp[ic];
            const float4* w4 = (const float4*)(wr + ic*32);
#pragma unroll
            for (int j = 0; j < 8; j++) {
                float4 w = w4[j];
                acc[j].x=fmaf(v,w.x,acc[j].x); acc[j].y=fmaf(v,w.y,acc[j].y);
                acc[j].z=fmaf(v,w.z,acc[j].z); acc[j].w=fmaf(v,w.w,acc[j].w);
            }
        }
    }
    size_t pix = (size_t)k*HWPIX + (size_t)y*WW + x;
    float v[32];
#pragma unroll
    for (int j = 0; j < 8; j++) {
        v[j*4]  =fmaxf(acc[j].x,0.f); v[j*4+1]=fmaxf(acc[j].y,0.f);
        v[j*4+2]=fmaxf(acc[j].z,0.f); v[j*4+3]=fmaxf(acc[j].w,0.f);
    }
#pragma unroll
    for (int q = 0; q < 4; q++)
        split_store8(g_bh + pix*64 + q*8, g_bl + pix*64 + q*8, v + q*8);
}

// ======================= conv weight preps =======================
__global__ void wprep_kernel(const float* __restrict__ kw, int which)
{
    int idx = blockIdx.x*256 + threadIdx.x;
    if (idx >= 73728) return;
    int t = idx / 36864, r = idx % 36864;
    int p = r >> 12, q = r & 4095;
    int oc = q >> 6, ic = q & 63;
    float w = kw[((size_t)p*64 + ic)*64 + oc];
    __nv_bfloat16 hb = __float2bfloat16(w);
    __nv_bfloat16 o = t ? __float2bfloat16(w - __bfloat162float(hb)) : hb;
    (which ? g_w2t : g_w1t)[idx] = o;
}

__global__ void wprep_sup2_kernel(const float* __restrict__ kw)
{
    int idx = blockIdx.x*256 + threadIdx.x;
    if (idx >= 36864) return;
    int t = idx / 18432, r = idx % 18432;
    int tap = r >> 11, q = r & 2047;
    int oc = q >> 6, ic = q & 63;
    float w = (ic < 32) ? kw[((size_t)tap*32 + ic)*32 + oc] : 0.f;
    __nv_bfloat16 hb = __float2bfloat16(w);
    g_wst[idx] = t ? __float2bfloat16(w - __bfloat162float(hb)) : hb;
}

// ===== mma.sync 64->64 3x3 conv, 2 output rows/block, 512 threads =====
#define PITCH 136
#define WOFF  69632                 // strip: 4 rows * 136 * 128 = 69632
#define BOFF (WOFF + 147456)        // 217088
#define CONV_SMEM (BOFF + 256)      // 217344

template<int MODE>
__global__ void __launch_bounds__(512, 1) conv64_kernel(const float* __restrict__ bias)
{
    extern __shared__ char csm[];
    const uint32_t sb = smem_u32(csm);
    const int tid = threadIdx.x, wid = tid >> 5, lane = tid & 31;
    const int mw = wid & 7, nh = wid >> 3;
    const int y0 = blockIdx.x*2, k = blockIdx.y;
    const int g = lane >> 2, tg = lane & 3;

    {
        const __nv_bfloat16* ws = MODE ? g_w2t : g_w1t;
        for (int i = tid; i < 9216; i += 512) {
            uint4 v = *(const uint4*)(ws + i*8);
            *(uint4*)(csm + WOFF + SWZ(i*16)) = v;
        }
    }
    if (tid < 64) ((float*)(csm + BOFF))[tid] = bias[tid];

    const __nv_bfloat16* srcH = MODE ? g_bh : g_ah;
    const __nv_bfloat16* srcL = MODE ? g_bl : g_al;
    float* bs = (float*)(csm + BOFF);

    const uint32_t alane = (mw*16 + (lane & 15))*128 + (lane >> 4)*16;
    const uint32_t blane = ((lane & 7) + ((lane & 16) >> 1))*128 + (lane & 8)*2;

    for (int t = 0; t < 4; t++) {
        const int x0 = t*128;
        float acc[2][4][4];
#pragma unroll
        for (int r = 0; r < 2; r++)
#pragma unroll
            for (int s = 0; s < 4; s++)
#pragma unroll
                for (int j = 0; j < 4; j++) acc[r][s][j] = 0.f;

        for (int pass = 0; pass < 2; pass++) {
            const __nv_bfloat16* src = pass ? srcL : srcH;
            __syncthreads();
            // stage 4 window rows (y0-1 .. y0+2), 130 px, 64ch
            for (int idx = tid; idx < 4160; idx += 512) {
                int r = idx >> 3, c = idx & 7;
                int dyw = r/130, sx = r - dyw*130;
                int iy = y0 - 1 + dyw, ix = x0 + sx - 1;
                uint4 v = make_uint4(0,0,0,0);
                if (iy >= 0 && iy < HH && (unsigned)ix < WW)
                    v = *(const uint4*)(src + ((size_t)k*HWPIX + (size_t)iy*WW + ix)*64 + c*8);
                *(uint4*)(csm + SWZ((dyw*PITCH + sx)*128 + c*16)) = v;
            }
            __syncthreads();

            const int nterm = pass ? 1 : 2;
            for (int tap = 0; tap < 9; tap++) {
                int dy = tap/3, dxo = tap - dy*3;
#pragma unroll
                for (int kc = 0; kc < 4; kc++) {
                    uint32_t a00,a01,a02,a03, a10,a11,a12,a13;
                    LDSM4(a00,a01,a02,a03, sb + SWZ((dy*PITCH + dxo)*128 + alane + kc*32));
                    LDSM4(a10,a11,a12,a13, sb + SWZ(((dy+1)*PITCH + dxo)*128 + alane + kc*32));
                    for (int tm = 0; tm < nterm; tm++) {
                        uint32_t wb = sb + WOFF + tm*73728;
#pragma unroll
                        for (int ns = 0; ns < 2; ns++) {
                            uint32_t b0,b1,b2,b3;
                            LDSM4(b0,b1,b2,b3, wb + SWZ(tap*8192 + (nh*2+ns)*2048 + kc*32 + blane));
                            MMA16816(acc[0][ns*2],   a00,a01,a02,a03, b0,b1);
                            MMA16816(acc[0][ns*2+1], a00,a01,a02,a03, b2,b3);
                            MMA16816(acc[1][ns*2],   a10,a11,a12,a13, b0,b1);
                            MMA16816(acc[1][ns*2+1], a10,a11,a12,a13, b2,b3);
                        }
                    }
                }
            }
        }

        if (MODE == 0) {
#pragma unroll
            for (int r = 0; r < 2; r++)
#pragma unroll
            for (int s = 0; s < 4; s++) {
                int oc = nh*32 + s*8 + tg*2;
                float b0v = bs[oc], b1v = bs[oc+1];
#pragma unroll
                for (int half = 0; half < 2; half++) {
                    int px = mw*16 + g + half*8;
                    int gx = x0 + px;
                    size_t pix = (size_t)k*HWPIX + (size_t)(y0+r)*WW + gx;
                    float v0 = fmaxf(acc[r][s][half*2]   + b0v, 0.f);
                    float v1 = fmaxf(acc[r][s][half*2+1] + b1v, 0.f);
                    union { __nv_bfloat16 b[2]; uint32_t u; } H, L;
                    H.b[0] = __float2bfloat16(v0);
                    H.b[1] = __float2bfloat16(v1);
                    L.b[0] = __float2bfloat16(v0 - __bfloat162float(H.b[0]));
                    L.b[1] = __float2bfloat16(v1 - __bfloat162float(H.b[1]));
                    *(uint32_t*)(g_bh + pix*64 + oc) = H.u;
                    *(uint32_t*)(g_bl + pix*64 + oc) = L.u;
                }
            }
        } else {
            float* fsm = (float*)csm;
            for (int r = 0; r < 2; r++) {
                __syncthreads();
#pragma unroll
                for (int s = 0; s < 4; s++) {
                    int oc = nh*32 + s*8 + tg*2;
#pragma unroll
                    for (int half = 0; half < 2; half++) {
                        int px = mw*16 + g + half*8;
                        fsm[px*68 + oc]     = acc[r][s][half*2]   + bs[oc];
                        fsm[px*68 + oc + 1] = acc[r][s][half*2+1] + bs[oc+1];
                    }
                }
                __syncthreads();
                if (tid < 128) {
                    int gx = x0 + tid;
                    size_t pix = (size_t)k*HWPIX + (size_t)(y0+r)*WW + gx;
                    const uint4* ah4 = (const uint4*)(g_ah + pix*64);
                    const uint4* al4 = (const uint4*)(g_al + pix*64);
                    float alpha = 1.f, fuse = 0.f;
#pragma unroll
                    for (int q = 0; q < 8; q++) {
                        union { uint4 u; __nv_bfloat16 b[8]; } Ha, La;
                        Ha.u = ah4[q]; La.u = al4[q];
#pragma unroll
                        for (int j = 0; j < 8; j++) {
                            float a = fsm[tid*68 + q*8 + j];
                            float m = 1.f/(1.f + expf(-a));
                            float f = __bfloat162float(Ha.b[j]) + __bfloat162float(La.b[j]);
                            fuse += f*m*alpha;
                            alpha *= (1.f - m);
                        }
                    }
                    g_fuse[((size_t)(y0+r)*WW + gx)*8 + k] = fuse;
                }
            }
        }
    }
}

// ===== sup2 tensor conv, 2 rows/block, 512 threads: 32 -> 32, no relu =====
#define W2OFF 69632
#define B2OFF (W2OFF + 73728)
#define SUP2_SMEM (B2OFF + 128)

__global__ void __launch_bounds__(512, 1) sup2_tc_kernel(const float* __restrict__ bias)
{
    extern __shared__ char csm[];
    const uint32_t sb = smem_u32(csm);
    const int tid = threadIdx.x, wid = tid >> 5, lane = tid & 31;
    const int mw = wid & 7, nh = wid >> 3;
    const int y0 = blockIdx.x*2, k = blockIdx.y;
    const int g = lane >> 2, tg = lane & 3;

    for (int i = tid; i < 4608; i += 512) {
        uint4 v = *(const uint4*)(g_wst + i*8);
        *(uint4*)(csm + W2OFF + SWZ(i*16)) = v;
    }
    if (tid < 32) ((float*)(csm + B2OFF))[tid] = bias[tid];
    float* bs = (float*)(csm + B2OFF);

    const uint32_t alane = (mw*16 + (lane & 15))*128 + (lane >> 4)*16;
    const uint32_t blane = ((lane & 7) + ((lane & 16) >> 1))*128 + (lane & 8)*2;

    for (int t = 0; t < 4; t++) {
        const int x0 = t*128;
        float acc[2][2][4];
#pragma unroll
        for (int r = 0; r < 2; r++)
#pragma unroll
            for (int s = 0; s < 2; s++)
#pragma unroll
                for (int j = 0; j < 4; j++) acc[r][s][j] = 0.f;

        for (int pass = 0; pass < 2; pass++) {
            const __nv_bfloat16* src = pass ? g_bl : g_bh;
            __syncthreads();
            for (int idx = tid; idx < 2080; idx += 512) {
                int r = idx >> 2, c = idx & 3;
                int dyw = r/130, sx = r - dyw*130;
                int iy = y0 - 1 + dyw, ix = x0 + sx - 1;
                uint4 v = make_uint4(0,0,0,0);
                if (iy >= 0 && iy < HH && (unsigned)ix < WW)
                    v = *(const uint4*)(src + ((size_t)k*HWPIX + (size_t)iy*WW + ix)*64 + c*8);
                *(uint4*)(csm + SWZ((dyw*PITCH + sx)*128 + c*16)) = v;
            }
            __syncthreads();

            const int nterm = pass ? 1 : 2;
            for (int tap = 0; tap < 9; tap++) {
                int dy = tap/3, dxo = tap - dy*3;
#pragma unroll
                for (int kc = 0; kc < 2; kc++) {
                    uint32_t a00,a01,a02,a03, a10,a11,a12,a13;
                    LDSM4(a00,a01,a02,a03, sb + SWZ((dy*PITCH + dxo)*128 + alane + kc*32));
                    LDSM4(a10,a11,a12,a13, sb + SWZ(((dy+1)*PITCH + dxo)*128 + alane + kc*32));
                    for (int tm = 0; tm < nterm; tm++) {
                        uint32_t wb = sb + W2OFF + tm*36864;
                        uint32_t b0,b1,b2,b3;
                        LDSM4(b0,b1,b2,b3, wb + SWZ(tap*4096 + nh*2048 + kc*32 + blane));
                        MMA16816(acc[0][0], a00,a01,a02,a03, b0,b1);
                        MMA16816(acc[0][1], a00,a01,a02,a03, b2,b3);
                        MMA16816(acc[1][0], a10,a11,a12,a13, b0,b1);
                        MMA16816(acc[1][1], a10,a11,a12,a13, b2,b3);
                    }
                }
            }
        }

#pragma unroll
        for (int r = 0; r < 2; r++)
#pragma unroll
        for (int s = 0; s < 2; s++) {
            int oc = nh*16 + s*8 + tg*2;
            float b0v = bs[oc], b1v = bs[oc+1];
#pragma unroll
            for (int half = 0; half < 2; half++) {
                int px = mw*16 + g + half*8;
                int gx = x0 + px;
                size_t pix = (size_t)k*HWPIX + (size_t)(y0+r)*WW + gx;
                float v0 = acc[r][s][half*2]   + b0v;
                float v1 = acc[r][s][half*2+1] + b1v;
                union { __nv_bfloat16 b[2]; uint32_t u; } H, L;
                H.b[0] = __float2bfloat16(v0);
                H.b[1] = __float2bfloat16(v1);
                L.b[0] = __float2bfloat16(v0 - __bfloat162float(H.b[0]));
                L.b[1] = __float2bfloat16(v1 - __bfloat162float(H.b[1]));
                *(uint32_t*)(g_ah + pix*64 + 32 + oc) = H.u;
                *(uint32_t*)(g_al + pix*64 + 32 + oc) = L.u;
            }
        }
    }
}

// ======================= un1: 8 -> 32 relu =======================
__global__ void un1_kernel(const float* __restrict__ kw, const float* __restrict__ bw)
{
    __shared__ float wgt[2304];
    int tx = threadIdx.x, ty = threadIdx.y, tid = ty*32 + tx;
    for (int i = tid; i < 2304; i += 256) wgt[i] = kw[i];
    __syncthreads();
    int x = blockIdx.x*32 + tx, y = blockIdx.y*8 + ty;
    float4 acc[8];
#pragma unroll
    for (int j = 0; j < 8; j++) acc[j] = ((const float4*)bw)[j];
    for (int dy = 0; dy < 3; dy++)
    for (int dx = 0; dx < 3; dx++) {
        int iy = y + dy - 1, ix = x + dx - 1;
        if (iy < 0 || iy >= HH || ix < 0 || ix >= WW) continue;
        const float* fp = g_fuse + ((size_t)iy*WW + ix)*8;
        float4 f0 = ((const float4*)fp)[0];
        float4 f1 = ((const float4*)fp)[1];
        float fv[8] = {f0.x,f0.y,f0.z,f0.w,f1.x,f1.y,f1.z,f1.w};
        const float* wr = wgt + (dy*3 + dx)*256;
#pragma unroll
        for (int ic = 0; ic < 8; ic++) {
            float v = fv[ic];
            const float4* w4 = (const float4*)(wr + ic*32);
#pragma unroll
            for (int j = 0; j < 8; j++) {
                float4 w = w4[j];
                acc[j].x=fmaf(v,w.x,acc[j].x); acc[j].y=fmaf(v,w.y,acc[j].y);
                acc[j].z=fmaf(v,w.z,acc[j].z); acc[j].w=fmaf(v,w.w,acc[j].w);
            }
        }
    }
    float* dst = g_u32 + ((size_t)y*WW + x)*32;
#pragma unroll
    for (int j = 0; j < 8; j++) {
        float4 o;
        o.x=fmaxf(acc[j].x,0.f); o.y=fmaxf(acc[j].y,0.f);
        o.z=fmaxf(acc[j].z,0.f); o.w=fmaxf(acc[j].w,0.f);
        ((float4*)dst)[j] = o;
    }
}

// ======================= un2: 32 -> 3 =======================
__global__ void un2_kernel(const float* __restrict__ kw, const float* __restrict__ bw,
                           float* __restrict__ out)
{
    __shared__ float wgt[864];
    int tx = threadIdx.x, ty = threadIdx.y, tid = ty*32 + tx;
    for (int i = tid; i < 864; i += 256) wgt[i] = kw[i];
    __syncthreads();
    int x = blockIdx.x*32 + tx, y = blockIdx.y*8 + ty;
    float a0 = bw[0], a1 = bw[1], a2 = bw[2];
    for (int dy = 0; dy < 3; dy++)
    for (int dx = 0; dx < 3; dx++) {
        int iy = y + dy - 1, ix = x + dx - 1;
        if (iy < 0 || iy >= HH || ix < 0 || ix >= WW) continue;
        const float* up = g_u32 + ((size_t)iy*WW + ix)*32;
        const float* wr = wgt + (dy*3 + dx)*96;
#pragma unroll
        for (int ic4 = 0; ic4 < 8; ic4++) {
            float4 v = ((const float4*)up)[ic4];
            float vv[4] = {v.x, v.y, v.z, v.w};
#pragma unroll
            for (int j = 0; j < 4; j++) {
                int ic = ic4*4 + j;
                a0 = fmaf(vv[j], wr[ic*3 + 0], a0);
                a1 = fmaf(vv[j], wr[ic*3 + 1], a1);
                a2 = fmaf(vv[j], wr[ic*3 + 2], a2);
            }
        }
    }
    float* dst = out + ((size_t)y*WW + x)*3;
    dst[0]=a0; dst[1]=a1; dst[2]=a2;
}

// ======================= launch =======================
extern "C" void kernel_launch(void* const* d_in, const int* in_sizes, int n_in,
                              void* d_out, int out_size)
{
    const float* colors = (const float*)d_in[0];
    const float* ray    = (const float*)d_in[1];
    const float* zbufs  = (const float*)d_in[2];
    const float* W1 = (const float*)d_in[3];  const float* b1 = (const float*)d_in[4];
    const float* W2 = (const float*)d_in[5];  const float* b2 = (const float*)d_in[6];
    const float* W3 = (const float*)d_in[7];  const float* b3 = (const float*)d_in[8];
    const float* W4 = (const float*)d_in[9];  const float* b4 = (const float*)d_in[10];
    const float* k_sup1 = (const float*)d_in[11]; const float* b_sup1 = (const float*)d_in[12];
    const float* k_sup2 = (const float*)d_in[13]; const float* b_sup2 = (const float*)d_in[14];
    const float* k_mpn1 = (const float*)d_in[15]; const float* b_mpn1 = (const float*)d_in[16];
    const float* k_mpn2 = (const float*)d_in[17]; const float* b_mpn2 = (const float*)d_in[18];
    const float* k_un1  = (const float*)d_in[19]; const float* b_un1  = (const float*)d_in[20];
    const float* k_un2  = (const float*)d_in[21]; const float* b_un2  = (const float*)d_in[22];
    float* out = (float*)d_out;

    static cudaStream_t sB = nullptr;
    static cudaEvent_t evRoot = nullptr, evB = nullptr;
    if (sB == nullptr) {
        cudaStreamCreateWithFlags(&sB, cudaStreamNonBlocking);
        cudaEventCreateWithFlags(&evRoot, cudaEventDisableTiming);
        cudaEventCreateWithFlags(&evB, cudaEventDisableTiming);
    }

    cudaFuncSetAttribute(mlp_tc_kernel, cudaFuncAttributeMaxDynamicSharedMemorySize, MLP_TC_SMEM);
    cudaFuncSetAttribute(sup2_tc_kernel, cudaFuncAttributeMaxDynamicSharedMemorySize, SUP2_SMEM);
    cudaFuncSetAttribute(conv64_kernel<0>, cudaFuncAttributeMaxDynamicSharedMemorySize, CONV_SMEM);
    cudaFuncSetAttribute(conv64_kernel<1>, cudaFuncAttributeMaxDynamicSharedMemorySize, CONV_SMEM);

    cudaEventRecord(evRoot, 0);
    cudaStreamWaitEvent(sB, evRoot, 0);

    mlpprep_kernel<<<144, 256>>>(W2, W3, W4);
    mlp_tc_kernel<<<148, 256, MLP_TC_SMEM>>>(ray, zbufs, W1, b1, b2, W3, b3, b4);

    wprep_kernel<<<288, 256, 0, sB>>>(k_mpn1, 0);
    wprep_kernel<<<288, 256, 0, sB>>>(k_mpn2, 1);
    wprep_sup2_kernel<<<144, 256, 0, sB>>>(k_sup2);
    sup1_kernel<<<dim3(16,64,8), dim3(32,8), 0, sB>>>(colors, k_sup1, b_sup1);
    sup2_tc_kernel<<<dim3(256,8), 512, SUP2_SMEM, sB>>>(b_sup2);

    cudaEventRecord(evB, sB);
    cudaStreamWaitEvent(0, evB, 0);

    conv64_kernel<0><<<dim3(256,8), 512, CONV_SMEM>>>(b_mpn1);
    conv64_kernel<1><<<dim3(256,8), 512, CONV_SMEM>>>(b_mpn2);
    un1_kernel<<<dim3(16,64), dim3(32,8)>>>(k_un1, b_un1);
    un2_kernel<<<dim3(16,64), dim3(32,8)>>>(k_un2, b_un2, out);
}